// round 1
// baseline (speedup 1.0000x reference)
#include <cuda_runtime.h>
#include <math.h>
#include <stdint.h>

#define NTOK   2048
#define FEAT   1024
#define IN_CH  12544
#define NONGT  300
#define G      16
#define DG     64
#define EMB    64
#define GW_STRIDE (G * NONGT)   // 4800

// ---------------- scratch (static device allocations, allowed) ----------------
__device__ float g_h   [NTOK * FEAT];
__device__ float g_h2  [NTOK * FEAT];
__device__ float g_q   [NTOK * FEAT];
__device__ float g_att [NTOK * FEAT];
__device__ float g_k   [NONGT * FEAT];
__device__ float g_P   [NONGT * FEAT];
__device__ float g_w   [NTOK * G * NONGT];

// ---------------- 128x128x16 tiled SIMT GEMM: C = A[M,K] @ W[N,K]^T + bias ----
__global__ __launch_bounds__(256, 2)
void gemm128(const float* __restrict__ A, const float* __restrict__ W,
             const float* __restrict__ bias, float* __restrict__ C,
             int M, int N, int K) {
    __shared__ float As[16][132];
    __shared__ float Ws[16][132];
    const int bm = blockIdx.y * 128;
    const int bn = blockIdx.x * 128;
    const int tid = threadIdx.x;
    const int tx = tid & 15;
    const int ty = tid >> 4;
    const int lrow = tid >> 2;          // 0..63
    const int lcol = (tid & 3) * 4;     // 0,4,8,12

    float acc[8][8];
#pragma unroll
    for (int i = 0; i < 8; i++)
#pragma unroll
        for (int j = 0; j < 8; j++) acc[i][j] = 0.f;

    for (int k0 = 0; k0 < K; k0 += 16) {
#pragma unroll
        for (int r = 0; r < 2; r++) {
            int row = lrow + r * 64;
            int gr = bm + row;
            float4 v = make_float4(0.f, 0.f, 0.f, 0.f);
            if (gr < M) v = *(const float4*)(A + (size_t)gr * K + k0 + lcol);
            As[lcol + 0][row] = v.x; As[lcol + 1][row] = v.y;
            As[lcol + 2][row] = v.z; As[lcol + 3][row] = v.w;
        }
#pragma unroll
        for (int r = 0; r < 2; r++) {
            int row = lrow + r * 64;
            int gr = bn + row;
            float4 v = make_float4(0.f, 0.f, 0.f, 0.f);
            if (gr < N) v = *(const float4*)(W + (size_t)gr * K + k0 + lcol);
            Ws[lcol + 0][row] = v.x; Ws[lcol + 1][row] = v.y;
            Ws[lcol + 2][row] = v.z; Ws[lcol + 3][row] = v.w;
        }
        __syncthreads();
#pragma unroll
        for (int k = 0; k < 16; k++) {
            float a[8], b[8];
            *(float4*)(a)     = *(const float4*)&As[k][ty * 8];
            *(float4*)(a + 4) = *(const float4*)&As[k][ty * 8 + 4];
            *(float4*)(b)     = *(const float4*)&Ws[k][tx * 8];
            *(float4*)(b + 4) = *(const float4*)&Ws[k][tx * 8 + 4];
#pragma unroll
            for (int i = 0; i < 8; i++)
#pragma unroll
                for (int j = 0; j < 8; j++) acc[i][j] = fmaf(a[i], b[j], acc[i][j]);
        }
        __syncthreads();
    }

#pragma unroll
    for (int i = 0; i < 8; i++) {
        int row = bm + ty * 8 + i;
        if (row < M) {
#pragma unroll
            for (int j = 0; j < 8; j++) {
                int col = bn + tx * 8 + j;
                if (col < N) {
                    float v = acc[i][j];
                    if (bias) v += bias[col];
                    C[(size_t)row * N + col] = v;
                }
            }
        }
    }
}

// ---------------- 64x64x16 variant (better parallelism for M=300 GEMMs) ------
__global__ __launch_bounds__(256)
void gemm64(const float* __restrict__ A, const float* __restrict__ W,
            const float* __restrict__ bias, float* __restrict__ C,
            int M, int N, int K) {
    __shared__ float As[16][68];
    __shared__ float Ws[16][68];
    const int bm = blockIdx.y * 64;
    const int bn = blockIdx.x * 64;
    const int tid = threadIdx.x;
    const int tx = tid & 15;
    const int ty = tid >> 4;
    const int lrow = tid >> 2;          // 0..63
    const int lcol = (tid & 3) * 4;

    float acc[4][4];
#pragma unroll
    for (int i = 0; i < 4; i++)
#pragma unroll
        for (int j = 0; j < 4; j++) acc[i][j] = 0.f;

    for (int k0 = 0; k0 < K; k0 += 16) {
        {
            int gr = bm + lrow;
            float4 v = make_float4(0.f, 0.f, 0.f, 0.f);
            if (gr < M) v = *(const float4*)(A + (size_t)gr * K + k0 + lcol);
            As[lcol + 0][lrow] = v.x; As[lcol + 1][lrow] = v.y;
            As[lcol + 2][lrow] = v.z; As[lcol + 3][lrow] = v.w;
        }
        {
            int gr = bn + lrow;
            float4 v = make_float4(0.f, 0.f, 0.f, 0.f);
            if (gr < N) v = *(const float4*)(W + (size_t)gr * K + k0 + lcol);
            Ws[lcol + 0][lrow] = v.x; Ws[lcol + 1][lrow] = v.y;
            Ws[lcol + 2][lrow] = v.z; Ws[lcol + 3][lrow] = v.w;
        }
        __syncthreads();
#pragma unroll
        for (int k = 0; k < 16; k++) {
            float a[4], b[4];
            *(float4*)a = *(const float4*)&As[k][ty * 4];
            *(float4*)b = *(const float4*)&Ws[k][tx * 4];
#pragma unroll
            for (int i = 0; i < 4; i++)
#pragma unroll
                for (int j = 0; j < 4; j++) acc[i][j] = fmaf(a[i], b[j], acc[i][j]);
        }
        __syncthreads();
    }

#pragma unroll
    for (int i = 0; i < 4; i++) {
        int row = bm + ty * 4 + i;
        if (row < M) {
#pragma unroll
            for (int j = 0; j < 4; j++) {
                int col = bn + tx * 4 + j;
                if (col < N) {
                    float v = acc[i][j];
                    if (bias) v += bias[col];
                    C[(size_t)row * N + col] = v;
                }
            }
        }
    }
}

// ---------------- pos logits: g_w[n][g][m] = log(max(pos_emb[n,m]·pos_w[g]+b, 1e-6))
__global__ __launch_bounds__(256)
void pos_logits(const float* __restrict__ pos_emb, const float* __restrict__ pw,
                const float* __restrict__ pb, float* __restrict__ Wt) {
    const int n  = blockIdx.y;
    const int m0 = blockIdx.x * 32;
    __shared__ float pe[32][65];
    __shared__ float pws[16][65];
    __shared__ float pbs[16];
    const int tid = threadIdx.x;

    if (tid < 16) pbs[tid] = pb[tid];
    {   // pos_w: 16x64
        int gg = tid >> 4, c = (tid & 15) * 4;
        float4 v = *(const float4*)(pw + gg * 64 + c);
        pws[gg][c + 0] = v.x; pws[gg][c + 1] = v.y;
        pws[gg][c + 2] = v.z; pws[gg][c + 3] = v.w;
    }
    {   // pos_emb tile: 32 rows x 64
        int r = tid >> 4;           // 0..15
        int c = (tid & 15) * 4;
#pragma unroll
        for (int rr = 0; rr < 2; rr++) {
            int row = r + rr * 16;
            int m = m0 + row;
            float4 v = make_float4(0.f, 0.f, 0.f, 0.f);
            if (m < NONGT) v = *(const float4*)(pos_emb + ((size_t)n * NONGT + m) * EMB + c);
            pe[row][c + 0] = v.x; pe[row][c + 1] = v.y;
            pe[row][c + 2] = v.z; pe[row][c + 3] = v.w;
        }
    }
    __syncthreads();

    const int w = tid >> 5, lane = tid & 31;
    const int m = m0 + lane;
    const int g0 = w * 2, g1 = w * 2 + 1;
    float acc0 = pbs[g0], acc1 = pbs[g1];
#pragma unroll
    for (int e = 0; e < 64; e++) {
        float p = pe[lane][e];
        acc0 = fmaf(p, pws[g0][e], acc0);
        acc1 = fmaf(p, pws[g1][e], acc1);
    }
    if (m < NONGT) {
        Wt[(size_t)n * GW_STRIDE + g0 * NONGT + m] = logf(fmaxf(acc0, 1e-6f));
        Wt[(size_t)n * GW_STRIDE + g1 * NONGT + m] = logf(fmaxf(acc1, 1e-6f));
    }
}

// ---------------- aff: g_w[n][g][m] += 0.125 * q[n,g,:]·k[m,g,:]  (batched per g)
__global__ __launch_bounds__(256)
void aff_add(const float* __restrict__ Q, const float* __restrict__ Kt,
             float* __restrict__ Wt) {
    const int g  = blockIdx.z;
    const int n0 = blockIdx.y * 64;
    const int m0 = blockIdx.x * 64;
    __shared__ float qs[64][68];   // [d][n_local]
    __shared__ float ks[64][68];   // [d][m_local]
    const int tid = threadIdx.x;
    const int row = tid >> 2;      // 0..63
    const int c0  = tid & 3;

    const float* qbase = Q + (size_t)(n0 + row) * FEAT + g * DG;
#pragma unroll
    for (int i = 0; i < 4; i++) {
        int d = (c0 + 4 * i) * 4;
        float4 v = *(const float4*)(qbase + d);
        qs[d + 0][row] = v.x; qs[d + 1][row] = v.y;
        qs[d + 2][row] = v.z; qs[d + 3][row] = v.w;
    }
    const int mrow = m0 + row;
#pragma unroll
    for (int i = 0; i < 4; i++) {
        int d = (c0 + 4 * i) * 4;
        float4 v = make_float4(0.f, 0.f, 0.f, 0.f);
        if (mrow < NONGT) v = *(const float4*)(Kt + (size_t)mrow * FEAT + g * DG + d);
        ks[d + 0][row] = v.x; ks[d + 1][row] = v.y;
        ks[d + 2][row] = v.z; ks[d + 3][row] = v.w;
    }
    __syncthreads();

    const int tx = tid & 15, ty = tid >> 4;
    float acc[4][4];
#pragma unroll
    for (int i = 0; i < 4; i++)
#pragma unroll
        for (int j = 0; j < 4; j++) acc[i][j] = 0.f;
#pragma unroll
    for (int d = 0; d < 64; d++) {
        float a[4], b[4];
        *(float4*)a = *(const float4*)&qs[d][ty * 4];
        *(float4*)b = *(const float4*)&ks[d][tx * 4];
#pragma unroll
        for (int i = 0; i < 4; i++)
#pragma unroll
            for (int j = 0; j < 4; j++) acc[i][j] = fmaf(a[i], b[j], acc[i][j]);
    }

#pragma unroll
    for (int i = 0; i < 4; i++) {
        int n = n0 + ty * 4 + i;
        float* wrow = Wt + (size_t)n * GW_STRIDE + g * NONGT;
#pragma unroll
        for (int j = 0; j < 4; j++) {
            int m = m0 + tx * 4 + j;
            if (m < NONGT) wrow[m] += 0.125f * acc[i][j];
        }
    }
}

// ---------------- softmax over m + out = s @ P_g + out_b ----------------------
__global__ __launch_bounds__(256)
void softmax_pv(const float* __restrict__ Wt, const float* __restrict__ P,
                const float* __restrict__ ob, float* __restrict__ Att) {
    const int g  = blockIdx.y;
    const int n0 = blockIdx.x * 16;
    __shared__ float s[16][301];
    const int tid = threadIdx.x, w = tid >> 5, lane = tid & 31;

#pragma unroll
    for (int rr = 0; rr < 2; rr++) {
        int r = w * 2 + rr;
        const float* src = Wt + (size_t)(n0 + r) * GW_STRIDE + g * NONGT;
        float v[10];
        float mx = -1e30f;
#pragma unroll
        for (int i = 0; i < 10; i++) {
            int m = lane + 32 * i;
            v[i] = (m < NONGT) ? src[m] : -1e30f;
            mx = fmaxf(mx, v[i]);
        }
#pragma unroll
        for (int off = 16; off; off >>= 1) mx = fmaxf(mx, __shfl_xor_sync(~0u, mx, off));
        float sum = 0.f;
#pragma unroll
        for (int i = 0; i < 10; i++) {
            float e = __expf(0.f) * 0.f + expf(v[i] - mx);  // plain expf
            if (lane + 32 * i >= NONGT) e = 0.f;
            v[i] = e;
            sum += e;
        }
#pragma unroll
        for (int off = 16; off; off >>= 1) sum += __shfl_xor_sync(~0u, sum, off);
        float inv = 1.f / sum;
#pragma unroll
        for (int i = 0; i < 10; i++) {
            int m = lane + 32 * i;
            if (m < NONGT) s[r][m] = v[i] * inv;
        }
    }
    __syncthreads();

    const int o = tid & 63, grp = tid >> 6;   // grp 0..3; rows grp, grp+4, grp+8, grp+12
    float acc0 = 0.f, acc1 = 0.f, acc2 = 0.f, acc3 = 0.f;
    const float* pcol = P + g * DG + o;
#pragma unroll 4
    for (int m = 0; m < NONGT; m++) {
        float p = __ldg(pcol + (size_t)m * FEAT);
        acc0 = fmaf(s[grp][m],      p, acc0);
        acc1 = fmaf(s[grp + 4][m],  p, acc1);
        acc2 = fmaf(s[grp + 8][m],  p, acc2);
        acc3 = fmaf(s[grp + 12][m], p, acc3);
    }
    float b = ob[g * DG + o];
    Att[(size_t)(n0 + grp)      * FEAT + g * DG + o] = acc0 + b;
    Att[(size_t)(n0 + grp + 4)  * FEAT + g * DG + o] = acc1 + b;
    Att[(size_t)(n0 + grp + 8)  * FEAT + g * DG + o] = acc2 + b;
    Att[(size_t)(n0 + grp + 12) * FEAT + g * DG + o] = acc3 + b;
}

// ---------------- elementwise: c = relu(a + b) --------------------------------
__global__ void add_relu4(const float4* __restrict__ a, const float4* __restrict__ b,
                          float4* __restrict__ c, int n4) {
    int i = blockIdx.x * blockDim.x + threadIdx.x;
    if (i < n4) {
        float4 x = a[i], y = b[i];
        float4 r;
        r.x = fmaxf(x.x + y.x, 0.f);
        r.y = fmaxf(x.y + y.y, 0.f);
        r.z = fmaxf(x.z + y.z, 0.f);
        r.w = fmaxf(x.w + y.w, 0.f);
        c[i] = r;
    }
}

// ---------------- orchestration ----------------------------------------------
static void run_attention(const float* h, const float* pos_emb,
                          const float* pw, const float* pb,
                          const float* qw, const float* qb,
                          const float* kw, const float* kb,
                          const float* ow, const float* ob,
                          float* q, float* kbuf, float* Pbuf, float* wbuf, float* att) {
    gemm128<<<dim3(FEAT / 128, NTOK / 128), 256>>>(h, qw, qb, q, NTOK, FEAT, FEAT);
    gemm64 <<<dim3(FEAT / 64, (NONGT + 63) / 64), 256>>>(h, kw, kb, kbuf, NONGT, FEAT, FEAT);
    gemm64 <<<dim3(FEAT / 64, (NONGT + 63) / 64), 256>>>(h, ow, nullptr, Pbuf, NONGT, FEAT, FEAT);
    pos_logits<<<dim3((NONGT + 31) / 32, NTOK), 256>>>(pos_emb, pw, pb, wbuf);
    aff_add<<<dim3((NONGT + 63) / 64, NTOK / 64, G), 256>>>(q, kbuf, wbuf);
    softmax_pv<<<dim3(NTOK / 16, G), 256>>>(wbuf, Pbuf, ob, att);
}

extern "C" void kernel_launch(void* const* d_in, const int* in_sizes, int n_in,
                              void* d_out, int out_size) {
    const float* x       = (const float*)d_in[0];
    const float* pos_emb = (const float*)d_in[1];
    const float* fc6_w   = (const float*)d_in[2];
    const float* fc6_b   = (const float*)d_in[3];
    const float* fc7_w   = (const float*)d_in[4];
    const float* fc7_b   = (const float*)d_in[5];
    const float* a1[8];
    const float* a2[8];
    for (int i = 0; i < 8; i++) a1[i] = (const float*)d_in[6 + i];
    for (int i = 0; i < 8; i++) a2[i] = (const float*)d_in[14 + i];
    // order within a block: pos_w, pos_b, q_w, q_b, k_w, k_b, out_w, out_b

    float *p_h, *p_h2, *p_q, *p_att, *p_k, *p_P, *p_w;
    cudaGetSymbolAddress((void**)&p_h,   g_h);
    cudaGetSymbolAddress((void**)&p_h2,  g_h2);
    cudaGetSymbolAddress((void**)&p_q,   g_q);
    cudaGetSymbolAddress((void**)&p_att, g_att);
    cudaGetSymbolAddress((void**)&p_k,   g_k);
    cudaGetSymbolAddress((void**)&p_P,   g_P);
    cudaGetSymbolAddress((void**)&p_w,   g_w);

    const int n4 = NTOK * FEAT / 4;

    // h = x @ fc6^T + b
    gemm128<<<dim3(FEAT / 128, NTOK / 128), 256>>>(x, fc6_w, fc6_b, p_h, NTOK, FEAT, IN_CH);

    // att1 = relation_attention(h)
    run_attention(p_h, pos_emb, a1[0], a1[1], a1[2], a1[3], a1[4], a1[5], a1[6], a1[7],
                  p_q, p_k, p_P, p_w, p_att);

    // h2 = relu(h + att1)
    add_relu4<<<(n4 + 255) / 256, 256>>>((const float4*)p_h, (const float4*)p_att,
                                         (float4*)p_h2, n4);

    // h = h2 @ fc7^T + b
    gemm128<<<dim3(FEAT / 128, NTOK / 128), 256>>>(p_h2, fc7_w, fc7_b, p_h, NTOK, FEAT, FEAT);

    // att2 = relation_attention(h)
    run_attention(p_h, pos_emb, a2[0], a2[1], a2[2], a2[3], a2[4], a2[5], a2[6], a2[7],
                  p_q, p_k, p_P, p_w, p_att);

    // out = relu(h + att2)
    add_relu4<<<(n4 + 255) / 256, 256>>>((const float4*)p_h, (const float4*)p_att,
                                         (float4*)d_out, n4);
}

// round 3
// speedup vs baseline: 1.2941x; 1.2941x over previous
#include <cuda_runtime.h>
#include <math.h>
#include <stdint.h>

#define NTOK   2048
#define FEAT   1024
#define IN_CH  12544
#define NONGT  300
#define G      16
#define DG     64
#define EMB    64
#define GW_STRIDE (G * NONGT)   // 4800

// GEMM tile config
#define BM 128
#define BN 128
#define BK 16
#define ASTR 20                  // smem row stride (floats): 20q+c covers all 32 banks
#define TILE_FLOATS (BM * ASTR)

// ---------------- scratch (static device arrays, allowed) ----------------
__device__ float g_h   [NTOK * FEAT];
__device__ float g_h2  [NTOK * FEAT];
__device__ float g_q   [NTOK * FEAT];
__device__ float g_att [NTOK * FEAT];
__device__ float g_k   [NONGT * FEAT];
__device__ float g_P   [NONGT * FEAT];
__device__ float g_w   [NTOK * G * NONGT];

// ---------------- helpers ----------------
__device__ __forceinline__ uint32_t cvta_s(const void* p) {
    return (uint32_t)__cvta_generic_to_shared(p);
}
__device__ __forceinline__ void cp16(uint32_t s, const void* g) {
    asm volatile("cp.async.cg.shared.global [%0], [%1], 16;\n" :: "r"(s), "l"(g));
}
// 3xTF32 split: f = hi + lo, both tf32-representable (stored as fp32 bit patterns)
__device__ __forceinline__ void split_tf32(float f, uint32_t& hi, uint32_t& lo) {
    uint32_t h;
    asm("cvt.rna.tf32.f32 %0, %1;" : "=r"(h) : "f"(f));
    float fl = f - __uint_as_float(h);
    asm("cvt.rna.tf32.f32 %0, %1;" : "=r"(lo) : "f"(fl));
    hi = h;
}
#define MMA_TF32(ACC, A0, A1, A2, A3, B0, B1)                                   \
    asm volatile(                                                               \
        "mma.sync.aligned.m16n8k8.row.col.f32.tf32.tf32.f32 "                   \
        "{%0,%1,%2,%3}, {%4,%5,%6,%7}, {%8,%9}, {%0,%1,%2,%3};\n"               \
        : "+f"(ACC[0]), "+f"(ACC[1]), "+f"(ACC[2]), "+f"(ACC[3])                \
        : "r"(A0), "r"(A1), "r"(A2), "r"(A3), "r"(B0), "r"(B1))

// ---------------- 3xTF32 tensor-core GEMM: C = A[M,K] @ W[N,K]^T (+bias) -----
// K % 16 == 0, N % 128 == 0. A must be readable up to row ceil(M/128)*128-1
// (all callers satisfy this: scratch buffers have 2048 rows, or M % 128 == 0).
__global__ __launch_bounds__(256)
void gemm_tc(const float* __restrict__ A, const float* __restrict__ W,
             const float* __restrict__ bias, float* __restrict__ C,
             int M, int N, int K) {
    __shared__ float As[2][TILE_FLOATS];
    __shared__ float Bs[2][TILE_FLOATS];

    const int tid  = threadIdx.x;
    const int lane = tid & 31;
    const int wid  = tid >> 5;
    const int wm   = wid >> 2;       // 0..1  (warp row)
    const int wn   = wid & 3;        // 0..3  (warp col)
    const int qd   = lane >> 2;      // 0..7
    const int tg   = lane & 3;       // 0..3
    const int bm   = blockIdx.y * BM;
    const int bn   = blockIdx.x * BN;

    // global load mapping: 4 threads per row, 16 floats (BK) per row
    const int lrow = tid >> 2;       // 0..63
    const int lcol = (tid & 3) * 4;  // 0,4,8,12
    const float* Ag = A + (size_t)(bm + lrow) * K + lcol;
    const float* Bg = W + (size_t)(bn + lrow) * K + lcol;

    const uint32_t sA = cvta_s(&As[0][lrow * ASTR + lcol]);
    const uint32_t sB = cvta_s(&Bs[0][lrow * ASTR + lcol]);
    const uint32_t bufBytes = TILE_FLOATS * 4;
    const uint32_t rowHalf  = 64 * ASTR * 4;

    float acc[4][4][4];
#pragma unroll
    for (int i = 0; i < 4; i++)
#pragma unroll
        for (int j = 0; j < 4; j++)
#pragma unroll
            for (int r = 0; r < 4; r++) acc[i][j][r] = 0.f;

    const int nk = K / BK;

    // prologue: stage k-tile 0 into buffer 0
    cp16(sA, Ag);           cp16(sA + rowHalf, Ag + (size_t)64 * K);
    cp16(sB, Bg);           cp16(sB + rowHalf, Bg + (size_t)64 * K);
    asm volatile("cp.async.commit_group;\n");

    for (int kt = 0; kt < nk; kt++) {
        const int cur = kt & 1;
        if (kt + 1 < nk) {
            const float* a2 = Ag + (size_t)(kt + 1) * BK;
            const float* b2 = Bg + (size_t)(kt + 1) * BK;
            const uint32_t off = (uint32_t)(cur ^ 1) * bufBytes;
            cp16(sA + off, a2);           cp16(sA + off + rowHalf, a2 + (size_t)64 * K);
            cp16(sB + off, b2);           cp16(sB + off + rowHalf, b2 + (size_t)64 * K);
        }
        asm volatile("cp.async.commit_group;\n");
        asm volatile("cp.async.wait_group 1;\n");
        __syncthreads();

        const float* as = As[cur];
        const float* bs = Bs[cur];

#pragma unroll
        for (int kk = 0; kk < 2; kk++) {
            const int kb = kk * 8 + tg;
            uint32_t ah[4][4], al[4][4];
#pragma unroll
            for (int mi = 0; mi < 4; mi++) {
                const int r = wm * 64 + mi * 16 + qd;
                split_tf32(as[r * ASTR + kb],           ah[mi][0], al[mi][0]);
                split_tf32(as[(r + 8) * ASTR + kb],     ah[mi][1], al[mi][1]);
                split_tf32(as[r * ASTR + kb + 4],       ah[mi][2], al[mi][2]);
                split_tf32(as[(r + 8) * ASTR + kb + 4], ah[mi][3], al[mi][3]);
            }
            uint32_t bh[4][2], bl[4][2];
#pragma unroll
            for (int ni = 0; ni < 4; ni++) {
                const int nn = wn * 32 + ni * 8 + qd;
                split_tf32(bs[nn * ASTR + kb],     bh[ni][0], bl[ni][0]);
                split_tf32(bs[nn * ASTR + kb + 4], bh[ni][1], bl[ni][1]);
            }
#pragma unroll
            for (int mi = 0; mi < 4; mi++)
#pragma unroll
                for (int ni = 0; ni < 4; ni++) {
                    // small terms first, then hi*hi
                    MMA_TF32(acc[mi][ni], al[mi][0], al[mi][1], al[mi][2], al[mi][3],
                             bh[ni][0], bh[ni][1]);
                    MMA_TF32(acc[mi][ni], ah[mi][0], ah[mi][1], ah[mi][2], ah[mi][3],
                             bl[ni][0], bl[ni][1]);
                    MMA_TF32(acc[mi][ni], ah[mi][0], ah[mi][1], ah[mi][2], ah[mi][3],
                             bh[ni][0], bh[ni][1]);
                }
        }
        __syncthreads();
    }

    // epilogue
#pragma unroll
    for (int mi = 0; mi < 4; mi++) {
        const int r0 = bm + wm * 64 + mi * 16 + qd;
#pragma unroll
        for (int ni = 0; ni < 4; ni++) {
            const int c0 = bn + wn * 32 + ni * 8 + tg * 2;
            const float b0 = bias ? bias[c0]     : 0.f;
            const float b1 = bias ? bias[c0 + 1] : 0.f;
            if (r0 < M)
                *(float2*)(C + (size_t)r0 * N + c0) =
                    make_float2(acc[mi][ni][0] + b0, acc[mi][ni][1] + b1);
            if (r0 + 8 < M)
                *(float2*)(C + (size_t)(r0 + 8) * N + c0) =
                    make_float2(acc[mi][ni][2] + b0, acc[mi][ni][3] + b1);
        }
    }
}

// ---------------- pos logits: g_w[n][g][m] = log(max(pos_emb[n,m]·pos_w[g]+b, 1e-6))
__global__ __launch_bounds__(256)
void pos_logits(const float* __restrict__ pos_emb, const float* __restrict__ pw,
                const float* __restrict__ pb, float* __restrict__ Wt) {
    const int n  = blockIdx.y;
    const int m0 = blockIdx.x * 32;
    __shared__ float pe[32][65];
    __shared__ float pws[16][65];
    __shared__ float pbs[16];
    const int tid = threadIdx.x;

    if (tid < 16) pbs[tid] = pb[tid];
    {
        int gg = tid >> 4, c = (tid & 15) * 4;
        float4 v = *(const float4*)(pw + gg * 64 + c);
        pws[gg][c + 0] = v.x; pws[gg][c + 1] = v.y;
        pws[gg][c + 2] = v.z; pws[gg][c + 3] = v.w;
    }
    {
        int r = tid >> 4;
        int c = (tid & 15) * 4;
#pragma unroll
        for (int rr = 0; rr < 2; rr++) {
            int row = r + rr * 16;
            int m = m0 + row;
            float4 v = make_float4(0.f, 0.f, 0.f, 0.f);
            if (m < NONGT) v = *(const float4*)(pos_emb + ((size_t)n * NONGT + m) * EMB + c);
            pe[row][c + 0] = v.x; pe[row][c + 1] = v.y;
            pe[row][c + 2] = v.z; pe[row][c + 3] = v.w;
        }
    }
    __syncthreads();

    const int w = tid >> 5, lane = tid & 31;
    const int m = m0 + lane;
    const int g0 = w * 2, g1 = w * 2 + 1;
    float acc0 = pbs[g0], acc1 = pbs[g1];
#pragma unroll
    for (int e = 0; e < 64; e++) {
        float p = pe[lane][e];
        acc0 = fmaf(p, pws[g0][e], acc0);
        acc1 = fmaf(p, pws[g1][e], acc1);
    }
    if (m < NONGT) {
        Wt[(size_t)n * GW_STRIDE + g0 * NONGT + m] = logf(fmaxf(acc0, 1e-6f));
        Wt[(size_t)n * GW_STRIDE + g1 * NONGT + m] = logf(fmaxf(acc1, 1e-6f));
    }
}

// ---------------- aff: g_w[n][g][m] += 0.125 * q[n,g,:]·k[m,g,:]  (batched per g)
__global__ __launch_bounds__(256)
void aff_add(const float* __restrict__ Q, const float* __restrict__ Kt,
             float* __restrict__ Wt) {
    const int g  = blockIdx.z;
    const int n0 = blockIdx.y * 64;
    const int m0 = blockIdx.x * 64;
    __shared__ float qs[64][68];
    __shared__ float ks[64][68];
    const int tid = threadIdx.x;
    const int row = tid >> 2;
    const int c0  = tid & 3;

    const float* qbase = Q + (size_t)(n0 + row) * FEAT + g * DG;
#pragma unroll
    for (int i = 0; i < 4; i++) {
        int d = (c0 + 4 * i) * 4;
        float4 v = *(const float4*)(qbase + d);
        qs[d + 0][row] = v.x; qs[d + 1][row] = v.y;
        qs[d + 2][row] = v.z; qs[d + 3][row] = v.w;
    }
    const int mrow = m0 + row;
#pragma unroll
    for (int i = 0; i < 4; i++) {
        int d = (c0 + 4 * i) * 4;
        float4 v = make_float4(0.f, 0.f, 0.f, 0.f);
        if (mrow < NONGT) v = *(const float4*)(Kt + (size_t)mrow * FEAT + g * DG + d);
        ks[d + 0][row] = v.x; ks[d + 1][row] = v.y;
        ks[d + 2][row] = v.z; ks[d + 3][row] = v.w;
    }
    __syncthreads();

    const int tx = tid & 15, ty = tid >> 4;
    float acc[4][4];
#pragma unroll
    for (int i = 0; i < 4; i++)
#pragma unroll
        for (int j = 0; j < 4; j++) acc[i][j] = 0.f;
#pragma unroll
    for (int d = 0; d < 64; d++) {
        float a[4], b[4];
        *(float4*)a = *(const float4*)&qs[d][ty * 4];
        *(float4*)b = *(const float4*)&ks[d][tx * 4];
#pragma unroll
        for (int i = 0; i < 4; i++)
#pragma unroll
            for (int j = 0; j < 4; j++) acc[i][j] = fmaf(a[i], b[j], acc[i][j]);
    }

#pragma unroll
    for (int i = 0; i < 4; i++) {
        int n = n0 + ty * 4 + i;
        float* wrow = Wt + (size_t)n * GW_STRIDE + g * NONGT;
#pragma unroll
        for (int j = 0; j < 4; j++) {
            int m = m0 + tx * 4 + j;
            if (m < NONGT) wrow[m] += 0.125f * acc[i][j];
        }
    }
}

// ---------------- softmax over m + out = s @ P_g + out_b ----------------------
__global__ __launch_bounds__(256)
void softmax_pv(const float* __restrict__ Wt, const float* __restrict__ P,
                const float* __restrict__ ob, float* __restrict__ Att) {
    const int g  = blockIdx.y;
    const int n0 = blockIdx.x * 16;
    __shared__ float s[16][301];
    const int tid = threadIdx.x, w = tid >> 5, lane = tid & 31;

#pragma unroll
    for (int rr = 0; rr < 2; rr++) {
        int r = w * 2 + rr;
        const float* src = Wt + (size_t)(n0 + r) * GW_STRIDE + g * NONGT;
        float v[10];
        float mx = -1e30f;
#pragma unroll
        for (int i = 0; i < 10; i++) {
            int m = lane + 32 * i;
            v[i] = (m < NONGT) ? src[m] : -1e30f;
            mx = fmaxf(mx, v[i]);
        }
#pragma unroll
        for (int off = 16; off; off >>= 1) mx = fmaxf(mx, __shfl_xor_sync(~0u, mx, off));
        float sum = 0.f;
#pragma unroll
        for (int i = 0; i < 10; i++) {
            float e = expf(v[i] - mx);
            if (lane + 32 * i >= NONGT) e = 0.f;
            v[i] = e;
            sum += e;
        }
#pragma unroll
        for (int off = 16; off; off >>= 1) sum += __shfl_xor_sync(~0u, sum, off);
        float inv = 1.f / sum;
#pragma unroll
        for (int i = 0; i < 10; i++) {
            int m = lane + 32 * i;
            if (m < NONGT) s[r][m] = v[i] * inv;
        }
    }
    __syncthreads();

    const int o = tid & 63, grp = tid >> 6;
    float acc0 = 0.f, acc1 = 0.f, acc2 = 0.f, acc3 = 0.f;
    const float* pcol = P + g * DG + o;
#pragma unroll 4
    for (int m = 0; m < NONGT; m++) {
        float p = __ldg(pcol + (size_t)m * FEAT);
        acc0 = fmaf(s[grp][m],      p, acc0);
        acc1 = fmaf(s[grp + 4][m],  p, acc1);
        acc2 = fmaf(s[grp + 8][m],  p, acc2);
        acc3 = fmaf(s[grp + 12][m], p, acc3);
    }
    float b = ob[g * DG + o];
    Att[(size_t)(n0 + grp)      * FEAT + g * DG + o] = acc0 + b;
    Att[(size_t)(n0 + grp + 4)  * FEAT + g * DG + o] = acc1 + b;
    Att[(size_t)(n0 + grp + 8)  * FEAT + g * DG + o] = acc2 + b;
    Att[(size_t)(n0 + grp + 12) * FEAT + g * DG + o] = acc3 + b;
}

// ---------------- elementwise: c = relu(a + b) --------------------------------
__global__ void add_relu4(const float4* __restrict__ a, const float4* __restrict__ b,
                          float4* __restrict__ c, int n4) {
    int i = blockIdx.x * blockDim.x + threadIdx.x;
    if (i < n4) {
        float4 x = a[i], y = b[i];
        float4 r;
        r.x = fmaxf(x.x + y.x, 0.f);
        r.y = fmaxf(x.y + y.y, 0.f);
        r.z = fmaxf(x.z + y.z, 0.f);
        r.w = fmaxf(x.w + y.w, 0.f);
        c[i] = r;
    }
}

// ---------------- orchestration ----------------------------------------------
static void run_attention(const float* h, const float* pos_emb,
                          const float* pw, const float* pb,
                          const float* qw, const float* qb,
                          const float* kw, const float* kb,
                          const float* ow, const float* ob,
                          float* q, float* kbuf, float* Pbuf, float* wbuf, float* att) {
    gemm_tc<<<dim3(FEAT / BN, NTOK / BM), 256>>>(h, qw, qb, q, NTOK, FEAT, FEAT);
    gemm_tc<<<dim3(FEAT / BN, (NONGT + BM - 1) / BM), 256>>>(h, kw, kb, kbuf, NONGT, FEAT, FEAT);
    gemm_tc<<<dim3(FEAT / BN, (NONGT + BM - 1) / BM), 256>>>(h, ow, nullptr, Pbuf, NONGT, FEAT, FEAT);
    pos_logits<<<dim3((NONGT + 31) / 32, NTOK), 256>>>(pos_emb, pw, pb, wbuf);
    aff_add<<<dim3((NONGT + 63) / 64, NTOK / 64, G), 256>>>(q, kbuf, wbuf);
    softmax_pv<<<dim3(NTOK / 16, G), 256>>>(wbuf, Pbuf, ob, att);
}

extern "C" void kernel_launch(void* const* d_in, const int* in_sizes, int n_in,
                              void* d_out, int out_size) {
    const float* x       = (const float*)d_in[0];
    const float* pos_emb = (const float*)d_in[1];
    const float* fc6_w   = (const float*)d_in[2];
    const float* fc6_b   = (const float*)d_in[3];
    const float* fc7_w   = (const float*)d_in[4];
    const float* fc7_b   = (const float*)d_in[5];
    const float* a1[8];
    const float* a2[8];
    for (int i = 0; i < 8; i++) a1[i] = (const float*)d_in[6 + i];
    for (int i = 0; i < 8; i++) a2[i] = (const float*)d_in[14 + i];

    float *p_h, *p_h2, *p_q, *p_att, *p_k, *p_P, *p_w;
    cudaGetSymbolAddress((void**)&p_h,   g_h);
    cudaGetSymbolAddress((void**)&p_h2,  g_h2);
    cudaGetSymbolAddress((void**)&p_q,   g_q);
    cudaGetSymbolAddress((void**)&p_att, g_att);
    cudaGetSymbolAddress((void**)&p_k,   g_k);
    cudaGetSymbolAddress((void**)&p_P,   g_P);
    cudaGetSymbolAddress((void**)&p_w,   g_w);

    const int n4 = NTOK * FEAT / 4;

    // h = x @ fc6^T + b   (K = 12544, tensor cores, 3xTF32)
    gemm_tc<<<dim3(FEAT / BN, NTOK / BM), 256>>>(x, fc6_w, fc6_b, p_h, NTOK, FEAT, IN_CH);

    run_attention(p_h, pos_emb, a1[0], a1[1], a1[2], a1[3], a1[4], a1[5], a1[6], a1[7],
                  p_q, p_k, p_P, p_w, p_att);

    add_relu4<<<(n4 + 255) / 256, 256>>>((const float4*)p_h, (const float4*)p_att,
                                         (float4*)p_h2, n4);

    gemm_tc<<<dim3(FEAT / BN, NTOK / BM), 256>>>(p_h2, fc7_w, fc7_b, p_h, NTOK, FEAT, FEAT);

    run_attention(p_h, pos_emb, a2[0], a2[1], a2[2], a2[3], a2[4], a2[5], a2[6], a2[7],
                  p_q, p_k, p_P, p_w, p_att);

    add_relu4<<<(n4 + 255) / 256, 256>>>((const float4*)p_h, (const float4*)p_att,
                                         (float4*)d_out, n4);
}

// round 5
// speedup vs baseline: 1.7844x; 1.3788x over previous
#include <cuda_runtime.h>
#include <cuda_fp16.h>
#include <math.h>
#include <stdint.h>

#define NTOK   2048
#define FEAT   1024
#define IN_CH  12544
#define NONGT  300
#define G      16
#define DG     64
#define EMB    64
#define GW_STRIDE (G * NONGT)   // 4800

// GEMM tile config
#define BM 128
#define BN 128
#define BK 16
#define ROWU 12                  // smem row stride in uint32 (48B): conflict-free
#define TILEU (128 * ROWU)       // uint32 per tile buffer

// ---------------- fp32 scratch ----------------
__device__ float g_h   [NTOK * FEAT];
__device__ float g_h2  [NTOK * FEAT];
__device__ float g_q   [NTOK * FEAT];
__device__ float g_att [NTOK * FEAT];
__device__ float g_kp  [384 * 2048];          // fused k|P output (rows 0..299 used)
__device__ float g_w   [NTOK * G * NONGT];
__device__ float g_bkp [2048];

// ---------------- fp16 split scratch ----------------
__device__ __half g_xh [NTOK * IN_CH];
__device__ __half g_xl [NTOK * IN_CH];
__device__ __half g_w6h[FEAT * IN_CH];
__device__ __half g_w6l[FEAT * IN_CH];
__device__ __half g_w7h[FEAT * FEAT];
__device__ __half g_w7l[FEAT * FEAT];
__device__ __half g_qwh[FEAT * FEAT];
__device__ __half g_qwl[FEAT * FEAT];
__device__ __half g_kpwh[2048 * FEAT];
__device__ __half g_kpwl[2048 * FEAT];
__device__ __half g_ah [NTOK * FEAT];
__device__ __half g_al [NTOK * FEAT];

// ---------------- helpers ----------------
__device__ __forceinline__ uint32_t cvta_s(const void* p) {
    return (uint32_t)__cvta_generic_to_shared(p);
}
__device__ __forceinline__ void cp16(uint32_t s, const void* g) {
    asm volatile("cp.async.cg.shared.global [%0], [%1], 16;\n" :: "r"(s), "l"(g));
}
#define MMA16(ACC, A0, A1, A2, A3, B0, B1)                                      \
    asm volatile(                                                               \
        "mma.sync.aligned.m16n8k16.row.col.f32.f16.f16.f32 "                    \
        "{%0,%1,%2,%3}, {%4,%5,%6,%7}, {%8,%9}, {%0,%1,%2,%3};\n"               \
        : "+f"(ACC[0]), "+f"(ACC[1]), "+f"(ACC[2]), "+f"(ACC[3])                \
        : "r"(A0), "r"(A1), "r"(A2), "r"(A3), "r"(B0), "r"(B1))

// ---------------- fp16x3 tensor-core GEMM: C = A[M,K] @ W[N,K]^T (+bias) -----
// A,W given as pre-split (hi,lo) fp16 arrays. K % 16 == 0, N % 128 == 0.
// A must be readable up to row ceil(M/128)*128-1 (scratch has 2048 rows).
__global__ __launch_bounds__(256, 2)
void gemm_f16x3(const __half* __restrict__ Ah, const __half* __restrict__ Al,
                const __half* __restrict__ Wh, const __half* __restrict__ Wl,
                const float* __restrict__ bias, float* __restrict__ C,
                int M, int N, int K) {
    __shared__ uint32_t sAh[2][TILEU], sAl[2][TILEU];
    __shared__ uint32_t sBh[2][TILEU], sBl[2][TILEU];

    const int tid  = threadIdx.x;
    const int lane = tid & 31;
    const int wid  = tid >> 5;
    const int wm   = wid >> 2;       // 0..1
    const int wn   = wid & 3;        // 0..3
    const int qd   = lane >> 2;      // 0..7
    const int tg   = lane & 3;       // 0..3
    const int bm   = blockIdx.y * BM;
    const int bn   = blockIdx.x * BN;

    // cp.async mapping: 256 threads, 128 rows x 2 chunks (16B each) per tile
    const int row = tid >> 1;
    const int chk = (tid & 1) * 8;   // half offset within row
    const __half* gAh = Ah + (size_t)(bm + row) * K + chk;
    const __half* gAl = Al + (size_t)(bm + row) * K + chk;
    const __half* gBh = Wh + (size_t)(bn + row) * K + chk;
    const __half* gBl = Wl + (size_t)(bn + row) * K + chk;

    const uint32_t smem_off = (uint32_t)(row * ROWU * 4 + chk * 2);
    const uint32_t aAh = cvta_s(sAh[0]) + smem_off;
    const uint32_t aAl = cvta_s(sAl[0]) + smem_off;
    const uint32_t aBh = cvta_s(sBh[0]) + smem_off;
    const uint32_t aBl = cvta_s(sBl[0]) + smem_off;
    const uint32_t bufB = TILEU * 4;

    float acc[4][4][4];
#pragma unroll
    for (int i = 0; i < 4; i++)
#pragma unroll
        for (int j = 0; j < 4; j++)
#pragma unroll
            for (int r = 0; r < 4; r++) acc[i][j][r] = 0.f;

    const int nk = K / BK;

    // prologue
    cp16(aAh, gAh); cp16(aAl, gAl); cp16(aBh, gBh); cp16(aBl, gBl);
    asm volatile("cp.async.commit_group;\n");

    for (int kt = 0; kt < nk; kt++) {
        const int cur = kt & 1;
        if (kt + 1 < nk) {
            const uint32_t off = (uint32_t)(cur ^ 1) * bufB;
            const size_t go = (size_t)(kt + 1) * BK;
            cp16(aAh + off, gAh + go); cp16(aAl + off, gAl + go);
            cp16(aBh + off, gBh + go); cp16(aBl + off, gBl + go);
        }
        asm volatile("cp.async.commit_group;\n");
        asm volatile("cp.async.wait_group 1;\n");
        __syncthreads();

        const uint32_t* ah = sAh[cur];
        const uint32_t* al = sAl[cur];
        const uint32_t* bh = sBh[cur];
        const uint32_t* bl = sBl[cur];

        uint32_t fah[4][4], fal[4][4];
#pragma unroll
        for (int mi = 0; mi < 4; mi++) {
            const int r0 = (wm * 64 + mi * 16 + qd) * ROWU;
            const int r8 = r0 + 8 * ROWU;
            fah[mi][0] = ah[r0 + tg];     fah[mi][1] = ah[r8 + tg];
            fah[mi][2] = ah[r0 + 4 + tg]; fah[mi][3] = ah[r8 + 4 + tg];
            fal[mi][0] = al[r0 + tg];     fal[mi][1] = al[r8 + tg];
            fal[mi][2] = al[r0 + 4 + tg]; fal[mi][3] = al[r8 + 4 + tg];
        }
        uint32_t fbh[4][2], fbl[4][2];
#pragma unroll
        for (int ni = 0; ni < 4; ni++) {
            const int nr = (wn * 32 + ni * 8 + qd) * ROWU;
            fbh[ni][0] = bh[nr + tg]; fbh[ni][1] = bh[nr + 4 + tg];
            fbl[ni][0] = bl[nr + tg]; fbl[ni][1] = bl[nr + 4 + tg];
        }
#pragma unroll
        for (int mi = 0; mi < 4; mi++)
#pragma unroll
            for (int ni = 0; ni < 4; ni++) {
                MMA16(acc[mi][ni], fal[mi][0], fal[mi][1], fal[mi][2], fal[mi][3],
                      fbh[ni][0], fbh[ni][1]);
                MMA16(acc[mi][ni], fah[mi][0], fah[mi][1], fah[mi][2], fah[mi][3],
                      fbl[ni][0], fbl[ni][1]);
                MMA16(acc[mi][ni], fah[mi][0], fah[mi][1], fah[mi][2], fah[mi][3],
                      fbh[ni][0], fbh[ni][1]);
            }
        __syncthreads();
    }

    // epilogue (same layout as m16n8 tf32 path)
#pragma unroll
    for (int mi = 0; mi < 4; mi++) {
        const int r0 = bm + wm * 64 + mi * 16 + qd;
#pragma unroll
        for (int ni = 0; ni < 4; ni++) {
            const int c0 = bn + wn * 32 + ni * 8 + tg * 2;
            const float b0 = bias ? bias[c0]     : 0.f;
            const float b1 = bias ? bias[c0 + 1] : 0.f;
            if (r0 < M)
                *(float2*)(C + (size_t)r0 * N + c0) =
                    make_float2(acc[mi][ni][0] + b0, acc[mi][ni][1] + b1);
            if (r0 + 8 < M)
                *(float2*)(C + (size_t)(r0 + 8) * N + c0) =
                    make_float2(acc[mi][ni][2] + b0, acc[mi][ni][3] + b1);
        }
    }
}

// ---------------- split: fp32 -> (hi, lo) fp16 --------------------------------
__global__ void split_f16(const float4* __restrict__ src, __half2* __restrict__ dh,
                          __half2* __restrict__ dl, int n4) {
    int i = blockIdx.x * blockDim.x + threadIdx.x;
    if (i < n4) {
        float4 v = src[i];
        __half2 h0 = __floats2half2_rn(v.x, v.y);
        __half2 h1 = __floats2half2_rn(v.z, v.w);
        float2 f0 = __half22float2(h0);
        float2 f1 = __half22float2(h1);
        dh[i * 2]     = h0;
        dh[i * 2 + 1] = h1;
        dl[i * 2]     = __floats2half2_rn(v.x - f0.x, v.y - f0.y);
        dl[i * 2 + 1] = __floats2half2_rn(v.z - f1.x, v.w - f1.y);
    }
}

// ---------------- h2 = relu(a+b), emitted directly as fp16 split --------------
__global__ void addrelu_split(const float4* __restrict__ a, const float4* __restrict__ b,
                              __half2* __restrict__ dh, __half2* __restrict__ dl, int n4) {
    int i = blockIdx.x * blockDim.x + threadIdx.x;
    if (i < n4) {
        float4 x = a[i], y = b[i];
        float4 v;
        v.x = fmaxf(x.x + y.x, 0.f); v.y = fmaxf(x.y + y.y, 0.f);
        v.z = fmaxf(x.z + y.z, 0.f); v.w = fmaxf(x.w + y.w, 0.f);
        __half2 h0 = __floats2half2_rn(v.x, v.y);
        __half2 h1 = __floats2half2_rn(v.z, v.w);
        float2 f0 = __half22float2(h0);
        float2 f1 = __half22float2(h1);
        dh[i * 2]     = h0;
        dh[i * 2 + 1] = h1;
        dl[i * 2]     = __floats2half2_rn(v.x - f0.x, v.y - f0.y);
        dl[i * 2 + 1] = __floats2half2_rn(v.z - f1.x, v.w - f1.y);
    }
}

// ---------------- final: c = relu(a+b) fp32 -----------------------------------
__global__ void add_relu4(const float4* __restrict__ a, const float4* __restrict__ b,
                          float4* __restrict__ c, int n4) {
    int i = blockIdx.x * blockDim.x + threadIdx.x;
    if (i < n4) {
        float4 x = a[i], y = b[i];
        float4 r;
        r.x = fmaxf(x.x + y.x, 0.f); r.y = fmaxf(x.y + y.y, 0.f);
        r.z = fmaxf(x.z + y.z, 0.f); r.w = fmaxf(x.w + y.w, 0.f);
        c[i] = r;
    }
}

// ---------------- bias for fused k|P GEMM: [k_b, zeros] -----------------------
__global__ void build_bias_kp(const float* __restrict__ kb, float* __restrict__ dst) {
    int i = blockIdx.x * blockDim.x + threadIdx.x;
    if (i < 2048) dst[i] = (i < 1024) ? kb[i] : 0.f;
}

// ---------------- pos logits --------------------------------------------------
__global__ __launch_bounds__(256)
void pos_logits(const float* __restrict__ pos_emb, const float* __restrict__ pw,
                const float* __restrict__ pb, float* __restrict__ Wt) {
    const int n  = blockIdx.y;
    const int m0 = blockIdx.x * 32;
    __shared__ float pe[32][65];
    __shared__ float pws[16][65];
    __shared__ float pbs[16];
    const int tid = threadIdx.x;

    if (tid < 16) pbs[tid] = pb[tid];
    {
        int gg = tid >> 4, c = (tid & 15) * 4;
        float4 v = *(const float4*)(pw + gg * 64 + c);
        pws[gg][c + 0] = v.x; pws[gg][c + 1] = v.y;
        pws[gg][c + 2] = v.z; pws[gg][c + 3] = v.w;
    }
    {
        int r = tid >> 4;
        int c = (tid & 15) * 4;
#pragma unroll
        for (int rr = 0; rr < 2; rr++) {
            int rw = r + rr * 16;
            int m = m0 + rw;
            float4 v = make_float4(0.f, 0.f, 0.f, 0.f);
            if (m < NONGT) v = *(const float4*)(pos_emb + ((size_t)n * NONGT + m) * EMB + c);
            pe[rw][c + 0] = v.x; pe[rw][c + 1] = v.y;
            pe[rw][c + 2] = v.z; pe[rw][c + 3] = v.w;
        }
    }
    __syncthreads();

    const int w = tid >> 5, lane = tid & 31;
    const int m = m0 + lane;
    const int g0 = w * 2, g1 = w * 2 + 1;
    float acc0 = pbs[g0], acc1 = pbs[g1];
#pragma unroll
    for (int e = 0; e < 64; e++) {
        float p = pe[lane][e];
        acc0 = fmaf(p, pws[g0][e], acc0);
        acc1 = fmaf(p, pws[g1][e], acc1);
    }
    if (m < NONGT) {
        Wt[(size_t)n * GW_STRIDE + g0 * NONGT + m] = logf(fmaxf(acc0, 1e-6f));
        Wt[(size_t)n * GW_STRIDE + g1 * NONGT + m] = logf(fmaxf(acc1, 1e-6f));
    }
}

// ---------------- aff: Wt[n][g][m] += 0.125 * q[n,g,:]·k[m,g,:] ---------------
__global__ __launch_bounds__(256)
void aff_add(const float* __restrict__ Q, const float* __restrict__ Kt, int ldk,
             float* __restrict__ Wt) {
    const int g  = blockIdx.z;
    const int n0 = blockIdx.y * 64;
    const int m0 = blockIdx.x * 64;
    __shared__ float qs[64][68];
    __shared__ float ks[64][68];
    const int tid = threadIdx.x;
    const int row = tid >> 2;
    const int c0  = tid & 3;

    const float* qbase = Q + (size_t)(n0 + row) * FEAT + g * DG;
#pragma unroll
    for (int i = 0; i < 4; i++) {
        int d = (c0 + 4 * i) * 4;
        float4 v = *(const float4*)(qbase + d);
        qs[d + 0][row] = v.x; qs[d + 1][row] = v.y;
        qs[d + 2][row] = v.z; qs[d + 3][row] = v.w;
    }
    const int mrow = m0 + row;
#pragma unroll
    for (int i = 0; i < 4; i++) {
        int d = (c0 + 4 * i) * 4;
        float4 v = make_float4(0.f, 0.f, 0.f, 0.f);
        if (mrow < NONGT) v = *(const float4*)(Kt + (size_t)mrow * ldk + g * DG + d);
        ks[d + 0][row] = v.x; ks[d + 1][row] = v.y;
        ks[d + 2][row] = v.z; ks[d + 3][row] = v.w;
    }
    __syncthreads();

    const int tx = tid & 15, ty = tid >> 4;
    float acc[4][4];
#pragma unroll
    for (int i = 0; i < 4; i++)
#pragma unroll
        for (int j = 0; j < 4; j++) acc[i][j] = 0.f;
#pragma unroll
    for (int d = 0; d < 64; d++) {
        float a[4], b[4];
        *(float4*)a = *(const float4*)&qs[d][ty * 4];
        *(float4*)b = *(const float4*)&ks[d][tx * 4];
#pragma unroll
        for (int i = 0; i < 4; i++)
#pragma unroll
            for (int j = 0; j < 4; j++) acc[i][j] = fmaf(a[i], b[j], acc[i][j]);
    }

#pragma unroll
    for (int i = 0; i < 4; i++) {
        int n = n0 + ty * 4 + i;
        float* wrow = Wt + (size_t)n * GW_STRIDE + g * NONGT;
#pragma unroll
        for (int j = 0; j < 4; j++) {
            int m = m0 + tx * 4 + j;
            if (m < NONGT) wrow[m] += 0.125f * acc[i][j];
        }
    }
}

// ---------------- softmax over m + out = s @ P_g + out_b ----------------------
__global__ __launch_bounds__(256)
void softmax_pv(const float* __restrict__ Wt, const float* __restrict__ P, int ldp,
                const float* __restrict__ ob, float* __restrict__ Att) {
    const int g  = blockIdx.y;
    const int n0 = blockIdx.x * 16;
    __shared__ float s[16][301];
    const int tid = threadIdx.x, w = tid >> 5, lane = tid & 31;

#pragma unroll
    for (int rr = 0; rr < 2; rr++) {
        int r = w * 2 + rr;
        const float* src = Wt + (size_t)(n0 + r) * GW_STRIDE + g * NONGT;
        float v[10];
        float mx = -1e30f;
#pragma unroll
        for (int i = 0; i < 10; i++) {
            int m = lane + 32 * i;
            v[i] = (m < NONGT) ? src[m] : -1e30f;
            mx = fmaxf(mx, v[i]);
        }
#pragma unroll
        for (int off = 16; off; off >>= 1) mx = fmaxf(mx, __shfl_xor_sync(~0u, mx, off));
        float sum = 0.f;
#pragma unroll
        for (int i = 0; i < 10; i++) {
            float e = expf(v[i] - mx);
            if (lane + 32 * i >= NONGT) e = 0.f;
            v[i] = e;
            sum += e;
        }
#pragma unroll
        for (int off = 16; off; off >>= 1) sum += __shfl_xor_sync(~0u, sum, off);
        float inv = 1.f / sum;
#pragma unroll
        for (int i = 0; i < 10; i++) {
            int m = lane + 32 * i;
            if (m < NONGT) s[r][m] = v[i] * inv;
        }
    }
    __syncthreads();

    const int o = tid & 63, grp = tid >> 6;
    float acc0 = 0.f, acc1 = 0.f, acc2 = 0.f, acc3 = 0.f;
    const float* pcol = P + g * DG + o;
#pragma unroll 4
    for (int m = 0; m < NONGT; m++) {
        float p = __ldg(pcol + (size_t)m * ldp);
        acc0 = fmaf(s[grp][m],      p, acc0);
        acc1 = fmaf(s[grp + 4][m],  p, acc1);
        acc2 = fmaf(s[grp + 8][m],  p, acc2);
        acc3 = fmaf(s[grp + 12][m], p, acc3);
    }
    float b = ob[g * DG + o];
    Att[(size_t)(n0 + grp)      * FEAT + g * DG + o] = acc0 + b;
    Att[(size_t)(n0 + grp + 4)  * FEAT + g * DG + o] = acc1 + b;
    Att[(size_t)(n0 + grp + 8)  * FEAT + g * DG + o] = acc2 + b;
    Att[(size_t)(n0 + grp + 12) * FEAT + g * DG + o] = acc3 + b;
}

// ---------------- host-side helpers -------------------------------------------
static inline void split_launch(const float* src, __half* dh, __half* dl, int n) {
    int n4 = n / 4;
    split_f16<<<(n4 + 255) / 256, 256>>>((const float4*)src, (__half2*)dh, (__half2*)dl, n4);
}

extern "C" void kernel_launch(void* const* d_in, const int* in_sizes, int n_in,
                              void* d_out, int out_size) {
    const float* x       = (const float*)d_in[0];
    const float* pos_emb = (const float*)d_in[1];
    const float* fc6_w   = (const float*)d_in[2];
    const float* fc6_b   = (const float*)d_in[3];
    const float* fc7_w   = (const float*)d_in[4];
    const float* fc7_b   = (const float*)d_in[5];
    const float* a1[8];
    const float* a2[8];
    for (int i = 0; i < 8; i++) a1[i] = (const float*)d_in[6 + i];
    for (int i = 0; i < 8; i++) a2[i] = (const float*)d_in[14 + i];
    // per block: pos_w, pos_b, q_w, q_b, k_w, k_b, out_w, out_b

    float *p_h, *p_h2, *p_q, *p_att, *p_kp, *p_w, *p_bkp;
    cudaGetSymbolAddress((void**)&p_h,   g_h);
    cudaGetSymbolAddress((void**)&p_h2,  g_h2);
    cudaGetSymbolAddress((void**)&p_q,   g_q);
    cudaGetSymbolAddress((void**)&p_att, g_att);
    cudaGetSymbolAddress((void**)&p_kp,  g_kp);
    cudaGetSymbolAddress((void**)&p_w,   g_w);
    cudaGetSymbolAddress((void**)&p_bkp, g_bkp);

    __half *xh, *xl, *w6h, *w6l, *w7h, *w7l, *qwh, *qwl, *kpwh, *kpwl, *ahh, *all;
    cudaGetSymbolAddress((void**)&xh,   g_xh);
    cudaGetSymbolAddress((void**)&xl,   g_xl);
    cudaGetSymbolAddress((void**)&w6h,  g_w6h);
    cudaGetSymbolAddress((void**)&w6l,  g_w6l);
    cudaGetSymbolAddress((void**)&w7h,  g_w7h);
    cudaGetSymbolAddress((void**)&w7l,  g_w7l);
    cudaGetSymbolAddress((void**)&qwh,  g_qwh);
    cudaGetSymbolAddress((void**)&qwl,  g_qwl);
    cudaGetSymbolAddress((void**)&kpwh, g_kpwh);
    cudaGetSymbolAddress((void**)&kpwl, g_kpwl);
    cudaGetSymbolAddress((void**)&ahh,  g_ah);
    cudaGetSymbolAddress((void**)&all,  g_al);

    const int n4 = NTOK * FEAT / 4;

    // ---- fc6: split inputs + weights, GEMM ----
    split_launch(x,     xh,  xl,  NTOK * IN_CH);
    split_launch(fc6_w, w6h, w6l, FEAT * IN_CH);
    split_launch(fc7_w, w7h, w7l, FEAT * FEAT);
    gemm_f16x3<<<dim3(FEAT / BN, NTOK / BM), 256>>>(xh, xl, w6h, w6l, fc6_b, p_h,
                                                    NTOK, FEAT, IN_CH);

    // ---- attention 1 ----
    split_launch(p_h, ahh, all, NTOK * FEAT);
    split_launch(a1[2], qwh, qwl, FEAT * FEAT);                       // q_w
    split_launch(a1[4], kpwh, kpwl, FEAT * FEAT);                     // k_w  -> rows 0..1023
    split_launch(a1[6], kpwh + 1024 * FEAT, kpwl + 1024 * FEAT, FEAT * FEAT);  // out_w
    build_bias_kp<<<8, 256>>>(a1[5], p_bkp);

    gemm_f16x3<<<dim3(FEAT / BN, NTOK / BM), 256>>>(ahh, all, qwh, qwl, a1[3], p_q,
                                                    NTOK, FEAT, FEAT);
    gemm_f16x3<<<dim3(2048 / BN, 3), 256>>>(ahh, all, kpwh, kpwl, p_bkp, p_kp,
                                            NONGT, 2048, FEAT);
    pos_logits<<<dim3((NONGT + 31) / 32, NTOK), 256>>>(pos_emb, a1[0], a1[1], p_w);
    aff_add<<<dim3((NONGT + 63) / 64, NTOK / 64, G), 256>>>(p_q, p_kp, 2048, p_w);
    softmax_pv<<<dim3(NTOK / 16, G), 256>>>(p_w, p_kp + 1024, 2048, a1[7], p_att);

    // ---- h2 = relu(h + att1), directly split for fc7 ----
    addrelu_split<<<(n4 + 255) / 256, 256>>>((const float4*)p_h, (const float4*)p_att,
                                             (__half2*)ahh, (__half2*)all, n4);

    // ---- fc7 ----
    gemm_f16x3<<<dim3(FEAT / BN, NTOK / BM), 256>>>(ahh, all, w7h, w7l, fc7_b, p_h2,
                                                    NTOK, FEAT, FEAT);

    // ---- attention 2 ----
    split_launch(p_h2, ahh, all, NTOK * FEAT);
    split_launch(a2[2], qwh, qwl, FEAT * FEAT);
    split_launch(a2[4], kpwh, kpwl, FEAT * FEAT);
    split_launch(a2[6], kpwh + 1024 * FEAT, kpwl + 1024 * FEAT, FEAT * FEAT);
    build_bias_kp<<<8, 256>>>(a2[5], p_bkp);

    gemm_f16x3<<<dim3(FEAT / BN, NTOK / BM), 256>>>(ahh, all, qwh, qwl, a2[3], p_q,
                                                    NTOK, FEAT, FEAT);
    gemm_f16x3<<<dim3(2048 / BN, 3), 256>>>(ahh, all, kpwh, kpwl, p_bkp, p_kp,
                                            NONGT, 2048, FEAT);
    pos_logits<<<dim3((NONGT + 31) / 32, NTOK), 256>>>(pos_emb, a2[0], a2[1], p_w);
    aff_add<<<dim3((NONGT + 63) / 64, NTOK / 64, G), 256>>>(p_q, p_kp, 2048, p_w);
    softmax_pv<<<dim3(NTOK / 16, G), 256>>>(p_w, p_kp + 1024, 2048, a2[7], p_att);

    // ---- out = relu(h2 + att2) ----
    add_relu4<<<(n4 + 255) / 256, 256>>>((const float4*)p_h2, (const float4*)p_att,
                                         (float4*)d_out, n4);
}

// round 8
// speedup vs baseline: 2.0173x; 1.1306x over previous
#include <cuda_runtime.h>
#include <cuda_fp16.h>
#include <math.h>
#include <stdint.h>

#define NTOK   2048
#define FEAT   1024
#define IN_CH  12544
#define NONGT  300
#define G      16
#define DG     64
#define EMB    64
#define GW_STRIDE (G * NONGT)   // 4800

// GEMM tile config: 128x128 CTA tile, BK=16, ldmatrix + 4-stage cp.async
#define ROWB   48                // smem row stride bytes (16 halves in first 32B)
#define TILEB  (128 * ROWB)      // 6144 B per operand tile
#define STGB   (4 * TILEB)       // Ah | Al | Bh | Bl = 24576 B
#define GSMEM  (4 * STGB)        // 4 stages = 98304 B

// ---------------- fp32 scratch ----------------
__device__ float g_h   [NTOK * FEAT];
__device__ float g_h2  [NTOK * FEAT];
__device__ float g_q   [NTOK * FEAT];
__device__ float g_att [NTOK * FEAT];
__device__ float g_kp  [384 * 2048];
__device__ float g_w   [NTOK * G * NONGT];     // pos weights (clamped, no log)
__device__ float g_aff [NTOK * G * NONGT];     // q.k affinities
__device__ float g_bkp [2048];

// ---------------- fp16 split scratch ----------------
__device__ __half g_xh [NTOK * IN_CH];
__device__ __half g_xl [NTOK * IN_CH];
__device__ __half g_w6h[FEAT * IN_CH];
__device__ __half g_w6l[FEAT * IN_CH];
__device__ __half g_w7h[FEAT * FEAT];
__device__ __half g_w7l[FEAT * FEAT];
__device__ __half g_qwh[FEAT * FEAT];
__device__ __half g_qwl[FEAT * FEAT];
__device__ __half g_kpwh[2048 * FEAT];
__device__ __half g_kpwl[2048 * FEAT];
__device__ __half g_ah [NTOK * FEAT];
__device__ __half g_al [NTOK * FEAT];

// ---------------- helpers ----------------
__device__ __forceinline__ uint32_t cvta_s(const void* p) {
    return (uint32_t)__cvta_generic_to_shared(p);
}
__device__ __forceinline__ void cp16(uint32_t s, const void* g) {
    asm volatile("cp.async.cg.shared.global [%0], [%1], 16;\n" :: "r"(s), "l"(g));
}
#define LDSM_X4(r0, r1, r2, r3, a)                                              \
    asm volatile("ldmatrix.sync.aligned.m8n8.x4.shared.b16 {%0,%1,%2,%3}, [%4];" \
                 : "=r"(r0), "=r"(r1), "=r"(r2), "=r"(r3) : "r"(a))
#define MMA16(ACC, A0, A1, A2, A3, B0, B1)                                      \
    asm volatile(                                                               \
        "mma.sync.aligned.m16n8k16.row.col.f32.f16.f16.f32 "                    \
        "{%0,%1,%2,%3}, {%4,%5,%6,%7}, {%8,%9}, {%0,%1,%2,%3};\n"               \
        : "+f"(ACC[0]), "+f"(ACC[1]), "+f"(ACC[2]), "+f"(ACC[3])                \
        : "r"(A0), "r"(A1), "r"(A2), "r"(A3), "r"(B0), "r"(B1))

// ---------------- fp16x3 GEMM (ldmatrix-fed): C = A[M,K] @ W[N,K]^T (+bias) --
// A,W pre-split (hi,lo) fp16. K % 16 == 0, N % 128 == 0. A readable up to row
// ceil(M/128)*128-1 (scratch buffers satisfy this).
__global__ __launch_bounds__(256, 2)
void gemm_lm(const __half* __restrict__ Ah, const __half* __restrict__ Al,
             const __half* __restrict__ Wh, const __half* __restrict__ Wl,
             const float* __restrict__ bias, float* __restrict__ C,
             int M, int N, int K) {
    extern __shared__ char dsm[];
    const uint32_t sbase = cvta_s(dsm);

    const int tid  = threadIdx.x;
    const int lane = tid & 31;
    const int wid  = tid >> 5;
    const int wm   = wid >> 2;       // 0..1
    const int wn   = wid & 3;        // 0..3
    const int qd   = lane >> 2;
    const int tg   = lane & 3;
    const int bm   = blockIdx.y * 128;
    const int bn   = blockIdx.x * 128;

    // cp.async: thread -> (row = tid/2, 16B chunk = tid&1)
    const int lrow = tid >> 1;
    const int lch  = tid & 1;
    const __half* gAh = Ah + (size_t)(bm + lrow) * K + lch * 8;
    const __half* gAl = Al + (size_t)(bm + lrow) * K + lch * 8;
    const __half* gBh = Wh + (size_t)(bn + lrow) * K + lch * 8;
    const __half* gBl = Wl + (size_t)(bn + lrow) * K + lch * 8;
    const uint32_t woff = (uint32_t)(lrow * ROWB + lch * 16);

    // ldmatrix lane addressing
    const uint32_t aRow  = (uint32_t)(wm * 64 + (lane & 7) + ((lane >> 3) & 1) * 8);
    const uint32_t aByte = (uint32_t)(((lane >> 4) & 1) * 16);
    const uint32_t bRow  = (uint32_t)(wn * 32 + ((lane >> 4) & 1) * 8 + (lane & 7));
    const uint32_t bByte = (uint32_t)(((lane >> 3) & 1) * 16);

    float acc[4][4][4];
#pragma unroll
    for (int i = 0; i < 4; i++)
#pragma unroll
        for (int j = 0; j < 4; j++)
#pragma unroll
            for (int r = 0; r < 4; r++) acc[i][j][r] = 0.f;

    const int nk = K / 16;

    auto load_stage = [&](int kt) {
        const uint32_t st = sbase + (uint32_t)(kt & 3) * STGB;
        const size_t k0 = (size_t)kt * 16;
        cp16(st + woff,             gAh + k0);
        cp16(st + TILEB + woff,     gAl + k0);
        cp16(st + 2 * TILEB + woff, gBh + k0);
        cp16(st + 3 * TILEB + woff, gBl + k0);
    };

    // prologue: stages 0..2
#pragma unroll
    for (int s = 0; s < 3; s++) {
        if (s < nk) load_stage(s);
        asm volatile("cp.async.commit_group;\n");
    }

    for (int kt = 0; kt < nk; kt++) {
        asm volatile("cp.async.wait_group 2;\n");
        __syncthreads();
        if (kt + 3 < nk) load_stage(kt + 3);
        asm volatile("cp.async.commit_group;\n");

        const uint32_t st  = sbase + (uint32_t)(kt & 3) * STGB;
        const uint32_t bhA = st + 2 * TILEB + bRow * ROWB + bByte;
        const uint32_t blA = st + 3 * TILEB + bRow * ROWB + bByte;

        uint32_t bh[4][2], bl[4][2];
        {
            uint32_t r0, r1, r2, r3;
            LDSM_X4(r0, r1, r2, r3, bhA);
            bh[0][0] = r0; bh[0][1] = r1; bh[1][0] = r2; bh[1][1] = r3;
            LDSM_X4(r0, r1, r2, r3, bhA + 16 * ROWB);
            bh[2][0] = r0; bh[2][1] = r1; bh[3][0] = r2; bh[3][1] = r3;
            LDSM_X4(r0, r1, r2, r3, blA);
            bl[0][0] = r0; bl[0][1] = r1; bl[1][0] = r2; bl[1][1] = r3;
            LDSM_X4(r0, r1, r2, r3, blA + 16 * ROWB);
            bl[2][0] = r0; bl[2][1] = r1; bl[3][0] = r2; bl[3][1] = r3;
        }
#pragma unroll
        for (int mi = 0; mi < 4; mi++) {
            const uint32_t ar = (aRow + mi * 16) * ROWB + aByte;
            uint32_t ah0, ah1, ah2, ah3, al0, al1, al2, al3;
            LDSM_X4(ah0, ah1, ah2, ah3, st + ar);
            LDSM_X4(al0, al1, al2, al3, st + TILEB + ar);
#pragma unroll
            for (int ni = 0; ni < 4; ni++) {
                MMA16(acc[mi][ni], al0, al1, al2, al3, bh[ni][0], bh[ni][1]);
                MMA16(acc[mi][ni], ah0, ah1, ah2, ah3, bl[ni][0], bl[ni][1]);
                MMA16(acc[mi][ni], ah0, ah1, ah2, ah3, bh[ni][0], bh[ni][1]);
            }
        }
    }

    // epilogue
#pragma unroll
    for (int mi = 0; mi < 4; mi++) {
        const int r0 = bm + wm * 64 + mi * 16 + qd;
#pragma unroll
        for (int ni = 0; ni < 4; ni++) {
            const int c0 = bn + wn * 32 + ni * 8 + tg * 2;
            const float b0 = bias ? bias[c0]     : 0.f;
            const float b1 = bias ? bias[c0 + 1] : 0.f;
            if (r0 < M)
                *(float2*)(C + (size_t)r0 * N + c0) =
                    make_float2(acc[mi][ni][0] + b0, acc[mi][ni][1] + b1);
            if (r0 + 8 < M)
                *(float2*)(C + (size_t)(r0 + 8) * N + c0) =
                    make_float2(acc[mi][ni][2] + b0, acc[mi][ni][3] + b1);
        }
    }
}

// ---------------- split: fp32 -> (hi, lo) fp16 --------------------------------
__global__ void split_f16(const float4* __restrict__ src, __half2* __restrict__ dh,
                          __half2* __restrict__ dl, int n4) {
    int i = blockIdx.x * blockDim.x + threadIdx.x;
    if (i < n4) {
        float4 v = src[i];
        __half2 h0 = __floats2half2_rn(v.x, v.y);
        __half2 h1 = __floats2half2_rn(v.z, v.w);
        float2 f0 = __half22float2(h0);
        float2 f1 = __half22float2(h1);
        dh[i * 2]     = h0;
        dh[i * 2 + 1] = h1;
        dl[i * 2]     = __floats2half2_rn(v.x - f0.x, v.y - f0.y);
        dl[i * 2 + 1] = __floats2half2_rn(v.z - f1.x, v.w - f1.y);
    }
}

// ---------------- h2 = relu(a+b), emitted directly as fp16 split --------------
__global__ void addrelu_split(const float4* __restrict__ a, const float4* __restrict__ b,
                              __half2* __restrict__ dh, __half2* __restrict__ dl, int n4) {
    int i = blockIdx.x * blockDim.x + threadIdx.x;
    if (i < n4) {
        float4 x = a[i], y = b[i];
        float4 v;
        v.x = fmaxf(x.x + y.x, 0.f); v.y = fmaxf(x.y + y.y, 0.f);
        v.z = fmaxf(x.z + y.z, 0.f); v.w = fmaxf(x.w + y.w, 0.f);
        __half2 h0 = __floats2half2_rn(v.x, v.y);
        __half2 h1 = __floats2half2_rn(v.z, v.w);
        float2 f0 = __half22float2(h0);
        float2 f1 = __half22float2(h1);
        dh[i * 2]     = h0;
        dh[i * 2 + 1] = h1;
        dl[i * 2]     = __floats2half2_rn(v.x - f0.x, v.y - f0.y);
        dl[i * 2 + 1] = __floats2half2_rn(v.z - f1.x, v.w - f1.y);
    }
}

// ---------------- final: c = relu(a+b) fp32 -----------------------------------
__global__ void add_relu4(const float4* __restrict__ a, const float4* __restrict__ b,
                          float4* __restrict__ c, int n4) {
    int i = blockIdx.x * blockDim.x + threadIdx.x;
    if (i < n4) {
        float4 x = a[i], y = b[i];
        float4 r;
        r.x = fmaxf(x.x + y.x, 0.f); r.y = fmaxf(x.y + y.y, 0.f);
        r.z = fmaxf(x.z + y.z, 0.f); r.w = fmaxf(x.w + y.w, 0.f);
        c[i] = r;
    }
}

// ---------------- bias for fused k|P GEMM: [k_b, zeros] -----------------------
__global__ void build_bias_kp(const float* __restrict__ kb, float* __restrict__ dst) {
    int i = blockIdx.x * blockDim.x + threadIdx.x;
    if (i < 2048) dst[i] = (i < 1024) ? kb[i] : 0.f;
}

// ---------------- pos weights: w[n][g][m] = max(relu(pe.pw+b), 1e-6) (NO log) --
__global__ __launch_bounds__(256)
void pos_logits(const float* __restrict__ pos_emb, const float* __restrict__ pw,
                const float* __restrict__ pb, float* __restrict__ Wt) {
    const int n  = blockIdx.y;
    const int m0 = blockIdx.x * 32;
    __shared__ float pe[32][65];
    __shared__ float pws[16][65];
    __shared__ float pbs[16];
    const int tid = threadIdx.x;

    if (tid < 16) pbs[tid] = pb[tid];
    {
        int gg = tid >> 4, c = (tid & 15) * 4;
        float4 v = *(const float4*)(pw + gg * 64 + c);
        pws[gg][c + 0] = v.x; pws[gg][c + 1] = v.y;
        pws[gg][c + 2] = v.z; pws[gg][c + 3] = v.w;
    }
    {
        int r = tid >> 4;
        int c = (tid & 15) * 4;
#pragma unroll
        for (int rr = 0; rr < 2; rr++) {
            int rw = r + rr * 16;
            int m = m0 + rw;
            float4 v = make_float4(0.f, 0.f, 0.f, 0.f);
            if (m < NONGT) v = *(const float4*)(pos_emb + ((size_t)n * NONGT + m) * EMB + c);
            pe[rw][c + 0] = v.x; pe[rw][c + 1] = v.y;
            pe[rw][c + 2] = v.z; pe[rw][c + 3] = v.w;
        }
    }
    __syncthreads();

    const int w = tid >> 5, lane = tid & 31;
    const int m = m0 + lane;
    const int g0 = w * 2, g1 = w * 2 + 1;
    float acc0 = pbs[g0], acc1 = pbs[g1];
#pragma unroll
    for (int e = 0; e < 64; e++) {
        float p = pe[lane][e];
        acc0 = fmaf(p, pws[g0][e], acc0);
        acc1 = fmaf(p, pws[g1][e], acc1);
    }
    if (m < NONGT) {
        Wt[(size_t)n * GW_STRIDE + g0 * NONGT + m] = fmaxf(acc0, 1e-6f);
        Wt[(size_t)n * GW_STRIDE + g1 * NONGT + m] = fmaxf(acc1, 1e-6f);
    }
}

// ---------------- aff: Aff[n][g][m] = 0.125 * q[n,g,:]·k[m,g,:] (pure store) --
__global__ __launch_bounds__(256)
void aff_add(const float* __restrict__ Q, const float* __restrict__ Kt, int ldk,
             float* __restrict__ Aff) {
    const int g  = blockIdx.z;
    const int n0 = blockIdx.y * 64;
    const int m0 = blockIdx.x * 64;
    __shared__ float qs[64][68];
    __shared__ float ks[64][68];
    const int tid = threadIdx.x;
    const int row = tid >> 2;
    const int c0  = tid & 3;

    const float* qbase = Q + (size_t)(n0 + row) * FEAT + g * DG;
#pragma unroll
    for (int i = 0; i < 4; i++) {
        int d = (c0 + 4 * i) * 4;
        float4 v = *(const float4*)(qbase + d);
        qs[d + 0][row] = v.x; qs[d + 1][row] = v.y;
        qs[d + 2][row] = v.z; qs[d + 3][row] = v.w;
    }
    const int mrow = m0 + row;
#pragma unroll
    for (int i = 0; i < 4; i++) {
        int d = (c0 + 4 * i) * 4;
        float4 v = make_float4(0.f, 0.f, 0.f, 0.f);
        if (mrow < NONGT) v = *(const float4*)(Kt + (size_t)mrow * ldk + g * DG + d);
        ks[d + 0][row] = v.x; ks[d + 1][row] = v.y;
        ks[d + 2][row] = v.z; ks[d + 3][row] = v.w;
    }
    __syncthreads();

    const int tx = tid & 15, ty = tid >> 4;
    float acc[4][4];
#pragma unroll
    for (int i = 0; i < 4; i++)
#pragma unroll
        for (int j = 0; j < 4; j++) acc[i][j] = 0.f;
#pragma unroll
    for (int d = 0; d < 64; d++) {
        float a[4], b[4];
        *(float4*)a = *(const float4*)&qs[d][ty * 4];
        *(float4*)b = *(const float4*)&ks[d][tx * 4];
#pragma unroll
        for (int i = 0; i < 4; i++)
#pragma unroll
            for (int j = 0; j < 4; j++) acc[i][j] = fmaf(a[i], b[j], acc[i][j]);
    }

#pragma unroll
    for (int i = 0; i < 4; i++) {
        int n = n0 + ty * 4 + i;
        float* arow = Aff + (size_t)n * GW_STRIDE + g * NONGT;
#pragma unroll
        for (int j = 0; j < 4; j++) {
            int m = m0 + tx * 4 + j;
            if (m < NONGT) arow[m] = 0.125f * acc[i][j];
        }
    }
}

// ---------------- softmax(w * e^aff) over m + out = s @ P_g + out_b ----------
__global__ __launch_bounds__(256)
void softmax_pv(const float* __restrict__ Wt, const float* __restrict__ Aff,
                const float* __restrict__ P, int ldp,
                const float* __restrict__ ob, float* __restrict__ Att) {
    const int g  = blockIdx.y;
    const int n0 = blockIdx.x * 16;
    __shared__ float s[16][301];
    const int tid = threadIdx.x, w = tid >> 5, lane = tid & 31;

#pragma unroll
    for (int rr = 0; rr < 2; rr++) {
        int r = w * 2 + rr;
        const float* srcW = Wt  + (size_t)(n0 + r) * GW_STRIDE + g * NONGT;
        const float* srcA = Aff + (size_t)(n0 + r) * GW_STRIDE + g * NONGT;
        float a[10], wv[10];
        float mx = -1e30f;
#pragma unroll
        for (int i = 0; i < 10; i++) {
            int m = lane + 32 * i;
            a[i]  = (m < NONGT) ? srcA[m] : -1e30f;
            wv[i] = (m < NONGT) ? srcW[m] : 0.f;
            mx = fmaxf(mx, a[i]);
        }
#pragma unroll
        for (int off = 16; off; off >>= 1) mx = fmaxf(mx, __shfl_xor_sync(~0u, mx, off));
        float sum = 0.f;
#pragma unroll
        for (int i = 0; i < 10; i++) {
            float e = wv[i] * __expf(a[i] - mx);
            a[i] = e;
            sum += e;
        }
#pragma unroll
        for (int off = 16; off; off >>= 1) sum += __shfl_xor_sync(~0u, sum, off);
        float inv = 1.f / sum;
#pragma unroll
        for (int i = 0; i < 10; i++) {
            int m = lane + 32 * i;
            if (m < NONGT) s[r][m] = a[i] * inv;
        }
    }
    __syncthreads();

    const int o = tid & 63, grp = tid >> 6;
    float acc0 = 0.f, acc1 = 0.f, acc2 = 0.f, acc3 = 0.f;
    const float* pcol = P + g * DG + o;
#pragma unroll 4
    for (int m = 0; m < NONGT; m++) {
        float p = __ldg(pcol + (size_t)m * ldp);
        acc0 = fmaf(s[grp][m],      p, acc0);
        acc1 = fmaf(s[grp + 4][m],  p, acc1);
        acc2 = fmaf(s[grp + 8][m],  p, acc2);
        acc3 = fmaf(s[grp + 12][m], p, acc3);
    }
    float b = ob[g * DG + o];
    Att[(size_t)(n0 + grp)      * FEAT + g * DG + o] = acc0 + b;
    Att[(size_t)(n0 + grp + 4)  * FEAT + g * DG + o] = acc1 + b;
    Att[(size_t)(n0 + grp + 8)  * FEAT + g * DG + o] = acc2 + b;
    Att[(size_t)(n0 + grp + 12) * FEAT + g * DG + o] = acc3 + b;
}

// ---------------- host-side helpers -------------------------------------------
static inline void split_launch(const float* src, __half* dh, __half* dl, int n) {
    int n4 = n / 4;
    split_f16<<<(n4 + 255) / 256, 256>>>((const float4*)src, (__half2*)dh, (__half2*)dl, n4);
}
static inline void gemm_launch(const __half* ah, const __half* al,
                               const __half* wh, const __half* wl,
                               const float* bias, float* c, int M, int N, int K) {
    dim3 grid(N / 128, (M + 127) / 128);
    gemm_lm<<<grid, 256, GSMEM>>>(ah, al, wh, wl, bias, c, M, N, K);
}

extern "C" void kernel_launch(void* const* d_in, const int* in_sizes, int n_in,
                              void* d_out, int out_size) {
    const float* x       = (const float*)d_in[0];
    const float* pos_emb = (const float*)d_in[1];
    const float* fc6_w   = (const float*)d_in[2];
    const float* fc6_b   = (const float*)d_in[3];
    const float* fc7_w   = (const float*)d_in[4];
    const float* fc7_b   = (const float*)d_in[5];
    const float* a1[8];
    const float* a2[8];
    for (int i = 0; i < 8; i++) a1[i] = (const float*)d_in[6 + i];
    for (int i = 0; i < 8; i++) a2[i] = (const float*)d_in[14 + i];
    // per block: pos_w, pos_b, q_w, q_b, k_w, k_b, out_w, out_b

    cudaFuncSetAttribute(gemm_lm, cudaFuncAttributeMaxDynamicSharedMemorySize, GSMEM);

    float *p_h, *p_h2, *p_q, *p_att, *p_kp, *p_w, *p_aff, *p_bkp;
    cudaGetSymbolAddress((void**)&p_h,   g_h);
    cudaGetSymbolAddress((void**)&p_h2,  g_h2);
    cudaGetSymbolAddress((void**)&p_q,   g_q);
    cudaGetSymbolAddress((void**)&p_att, g_att);
    cudaGetSymbolAddress((void**)&p_kp,  g_kp);
    cudaGetSymbolAddress((void**)&p_w,   g_w);
    cudaGetSymbolAddress((void**)&p_aff, g_aff);
    cudaGetSymbolAddress((void**)&p_bkp, g_bkp);

    __half *xh, *xl, *w6h, *w6l, *w7h, *w7l, *qwh, *qwl, *kpwh, *kpwl, *ahh, *all;
    cudaGetSymbolAddress((void**)&xh,   g_xh);
    cudaGetSymbolAddress((void**)&xl,   g_xl);
    cudaGetSymbolAddress((void**)&w6h,  g_w6h);
    cudaGetSymbolAddress((void**)&w6l,  g_w6l);
    cudaGetSymbolAddress((void**)&w7h,  g_w7h);
    cudaGetSymbolAddress((void**)&w7l,  g_w7l);
    cudaGetSymbolAddress((void**)&qwh,  g_qwh);
    cudaGetSymbolAddress((void**)&qwl,  g_qwl);
    cudaGetSymbolAddress((void**)&kpwh, g_kpwh);
    cudaGetSymbolAddress((void**)&kpwl, g_kpwl);
    cudaGetSymbolAddress((void**)&ahh,  g_ah);
    cudaGetSymbolAddress((void**)&all,  g_al);

    const int n4 = NTOK * FEAT / 4;

    // ---- fc6 ----
    split_launch(x,     xh,  xl,  NTOK * IN_CH);
    split_launch(fc6_w, w6h, w6l, FEAT * IN_CH);
    split_launch(fc7_w, w7h, w7l, FEAT * FEAT);
    gemm_launch(xh, xl, w6h, w6l, fc6_b, p_h, NTOK, FEAT, IN_CH);

    // ---- attention 1 ----
    split_launch(p_h, ahh, all, NTOK * FEAT);
    split_launch(a1[2], qwh, qwl, FEAT * FEAT);
    split_launch(a1[4], kpwh, kpwl, FEAT * FEAT);
    split_launch(a1[6], kpwh + 1024 * FEAT, kpwl + 1024 * FEAT, FEAT * FEAT);
    build_bias_kp<<<8, 256>>>(a1[5], p_bkp);

    gemm_launch(ahh, all, qwh, qwl, a1[3], p_q, NTOK, FEAT, FEAT);
    gemm_launch(ahh, all, kpwh, kpwl, p_bkp, p_kp, NONGT, 2048, FEAT);
    pos_logits<<<dim3((NONGT + 31) / 32, NTOK), 256>>>(pos_emb, a1[0], a1[1], p_w);
    aff_add<<<dim3((NONGT + 63) / 64, NTOK / 64, G), 256>>>(p_q, p_kp, 2048, p_aff);
    softmax_pv<<<dim3(NTOK / 16, G), 256>>>(p_w, p_aff, p_kp + 1024, 2048, a1[7], p_att);

    // ---- h2 = relu(h + att1), split for fc7 ----
    addrelu_split<<<(n4 + 255) / 256, 256>>>((const float4*)p_h, (const float4*)p_att,
                                             (__half2*)ahh, (__half2*)all, n4);

    // ---- fc7 ----
    gemm_launch(ahh, all, w7h, w7l, fc7_b, p_h2, NTOK, FEAT, FEAT);

    // ---- attention 2 ----
    split_launch(p_h2, ahh, all, NTOK * FEAT);
    split_launch(a2[2], qwh, qwl, FEAT * FEAT);
    split_launch(a2[4], kpwh, kpwl, FEAT * FEAT);
    split_launch(a2[6], kpwh + 1024 * FEAT, kpwl + 1024 * FEAT, FEAT * FEAT);
    build_bias_kp<<<8, 256>>>(a2[5], p_bkp);

    gemm_launch(ahh, all, qwh, qwl, a2[3], p_q, NTOK, FEAT, FEAT);
    gemm_launch(ahh, all, kpwh, kpwl, p_bkp, p_kp, NONGT, 2048, FEAT);
    pos_logits<<<dim3((NONGT + 31) / 32, NTOK), 256>>>(pos_emb, a2[0], a2[1], p_w);
    aff_add<<<dim3((NONGT + 63) / 64, NTOK / 64, G), 256>>>(p_q, p_kp, 2048, p_aff);
    softmax_pv<<<dim3(NTOK / 16, G), 256>>>(p_w, p_aff, p_kp + 1024, 2048, a2[7], p_att);

    // ---- out = relu(h2 + att2) ----
    add_relu4<<<(n4 + 255) / 256, 256>>>((const float4*)p_h2, (const float4*)p_att,
                                         (float4*)d_out, n4);
}

// round 9
// speedup vs baseline: 2.0174x; 1.0000x over previous
#include <cuda_runtime.h>
#include <cuda_fp16.h>
#include <math.h>
#include <stdint.h>

#define NTOK   2048
#define FEAT   1024
#define IN_CH  12544
#define NONGT  300
#define G      16
#define DG     64
#define EMB    64
#define GW_STRIDE (G * NONGT)   // 4800

// GEMM tile config: 128x128 CTA tile, BK=16, ldmatrix + 4-stage cp.async
#define ROWB   48                // smem row stride bytes (16 halves in first 32B)
#define TILEB  (128 * ROWB)      // 6144 B per operand tile
#define STGB   (4 * TILEB)       // Ah | Al | Bh | Bl = 24576 B
#define GSMEM  (4 * STGB)        // 4 stages = 98304 B

// ---------------- fp32 scratch ----------------
__device__ float g_h   [NTOK * FEAT];
__device__ float g_h2  [NTOK * FEAT];
__device__ float g_q   [NTOK * FEAT];
__device__ float g_att [NTOK * FEAT];
__device__ float g_kp  [384 * 2048];
__device__ float g_w   [NTOK * G * NONGT];     // pos weights (clamped, no log)
__device__ float g_aff [NTOK * G * NONGT];     // q.k affinities
__device__ float g_bkp [2048];

// ---------------- fp16 split scratch ----------------
__device__ __half g_xh [NTOK * IN_CH];
__device__ __half g_xl [NTOK * IN_CH];
__device__ __half g_w6h[FEAT * IN_CH];
__device__ __half g_w6l[FEAT * IN_CH];
__device__ __half g_w7h[FEAT * FEAT];
__device__ __half g_w7l[FEAT * FEAT];
__device__ __half g_qwh[FEAT * FEAT];
__device__ __half g_qwl[FEAT * FEAT];
__device__ __half g_kpwh[2048 * FEAT];
__device__ __half g_kpwl[2048 * FEAT];
__device__ __half g_ah [NTOK * FEAT];
__device__ __half g_al [NTOK * FEAT];

// ---------------- helpers ----------------
__device__ __forceinline__ uint32_t cvta_s(const void* p) {
    return (uint32_t)__cvta_generic_to_shared(p);
}
__device__ __forceinline__ void cp16(uint32_t s, const void* g) {
    asm volatile("cp.async.cg.shared.global [%0], [%1], 16;\n" :: "r"(s), "l"(g));
}
#define LDSM_X4(r0, r1, r2, r3, a)                                              \
    asm volatile("ldmatrix.sync.aligned.m8n8.x4.shared.b16 {%0,%1,%2,%3}, [%4];" \
                 : "=r"(r0), "=r"(r1), "=r"(r2), "=r"(r3) : "r"(a))
#define MMA16(ACC, A0, A1, A2, A3, B0, B1)                                      \
    asm volatile(                                                               \
        "mma.sync.aligned.m16n8k16.row.col.f32.f16.f16.f32 "                    \
        "{%0,%1,%2,%3}, {%4,%5,%6,%7}, {%8,%9}, {%0,%1,%2,%3};\n"               \
        : "+f"(ACC[0]), "+f"(ACC[1]), "+f"(ACC[2]), "+f"(ACC[3])                \
        : "r"(A0), "r"(A1), "r"(A2), "r"(A3), "r"(B0), "r"(B1))

// ---------------- fp16x3 GEMM (ldmatrix-fed): C = A[M,K] @ W[N,K]^T (+bias) --
// A,W pre-split (hi,lo) fp16. K % 16 == 0, N % 128 == 0. A readable up to row
// ceil(M/128)*128-1 (scratch buffers satisfy this).
__global__ __launch_bounds__(256, 2)
void gemm_lm(const __half* __restrict__ Ah, const __half* __restrict__ Al,
             const __half* __restrict__ Wh, const __half* __restrict__ Wl,
             const float* __restrict__ bias, float* __restrict__ C,
             int M, int N, int K) {
    extern __shared__ char dsm[];
    const uint32_t sbase = cvta_s(dsm);

    const int tid  = threadIdx.x;
    const int lane = tid & 31;
    const int wid  = tid >> 5;
    const int wm   = wid >> 2;       // 0..1
    const int wn   = wid & 3;        // 0..3
    const int qd   = lane >> 2;
    const int tg   = lane & 3;
    const int bm   = blockIdx.y * 128;
    const int bn   = blockIdx.x * 128;

    // cp.async: thread -> (row = tid/2, 16B chunk = tid&1)
    const int lrow = tid >> 1;
    const int lch  = tid & 1;
    const __half* gAh = Ah + (size_t)(bm + lrow) * K + lch * 8;
    const __half* gAl = Al + (size_t)(bm + lrow) * K + lch * 8;
    const __half* gBh = Wh + (size_t)(bn + lrow) * K + lch * 8;
    const __half* gBl = Wl + (size_t)(bn + lrow) * K + lch * 8;
    const uint32_t woff = (uint32_t)(lrow * ROWB + lch * 16);

    // ldmatrix lane addressing
    const uint32_t aRow  = (uint32_t)(wm * 64 + (lane & 7) + ((lane >> 3) & 1) * 8);
    const uint32_t aByte = (uint32_t)(((lane >> 4) & 1) * 16);
    const uint32_t bRow  = (uint32_t)(wn * 32 + ((lane >> 4) & 1) * 8 + (lane & 7));
    const uint32_t bByte = (uint32_t)(((lane >> 3) & 1) * 16);

    float acc[4][4][4];
#pragma unroll
    for (int i = 0; i < 4; i++)
#pragma unroll
        for (int j = 0; j < 4; j++)
#pragma unroll
            for (int r = 0; r < 4; r++) acc[i][j][r] = 0.f;

    const int nk = K / 16;

    auto load_stage = [&](int kt) {
        const uint32_t st = sbase + (uint32_t)(kt & 3) * STGB;
        const size_t k0 = (size_t)kt * 16;
        cp16(st + woff,             gAh + k0);
        cp16(st + TILEB + woff,     gAl + k0);
        cp16(st + 2 * TILEB + woff, gBh + k0);
        cp16(st + 3 * TILEB + woff, gBl + k0);
    };

    // prologue: stages 0..2
#pragma unroll
    for (int s = 0; s < 3; s++) {
        if (s < nk) load_stage(s);
        asm volatile("cp.async.commit_group;\n");
    }

    for (int kt = 0; kt < nk; kt++) {
        asm volatile("cp.async.wait_group 2;\n");
        __syncthreads();
        if (kt + 3 < nk) load_stage(kt + 3);
        asm volatile("cp.async.commit_group;\n");

        const uint32_t st  = sbase + (uint32_t)(kt & 3) * STGB;
        const uint32_t bhA = st + 2 * TILEB + bRow * ROWB + bByte;
        const uint32_t blA = st + 3 * TILEB + bRow * ROWB + bByte;

        uint32_t bh[4][2], bl[4][2];
        {
            uint32_t r0, r1, r2, r3;
            LDSM_X4(r0, r1, r2, r3, bhA);
            bh[0][0] = r0; bh[0][1] = r1; bh[1][0] = r2; bh[1][1] = r3;
            LDSM_X4(r0, r1, r2, r3, bhA + 16 * ROWB);
            bh[2][0] = r0; bh[2][1] = r1; bh[3][0] = r2; bh[3][1] = r3;
            LDSM_X4(r0, r1, r2, r3, blA);
            bl[0][0] = r0; bl[0][1] = r1; bl[1][0] = r2; bl[1][1] = r3;
            LDSM_X4(r0, r1, r2, r3, blA + 16 * ROWB);
            bl[2][0] = r0; bl[2][1] = r1; bl[3][0] = r2; bl[3][1] = r3;
        }
#pragma unroll
        for (int mi = 0; mi < 4; mi++) {
            const uint32_t ar = (aRow + mi * 16) * ROWB + aByte;
            uint32_t ah0, ah1, ah2, ah3, al0, al1, al2, al3;
            LDSM_X4(ah0, ah1, ah2, ah3, st + ar);
            LDSM_X4(al0, al1, al2, al3, st + TILEB + ar);
#pragma unroll
            for (int ni = 0; ni < 4; ni++) {
                MMA16(acc[mi][ni], al0, al1, al2, al3, bh[ni][0], bh[ni][1]);
                MMA16(acc[mi][ni], ah0, ah1, ah2, ah3, bl[ni][0], bl[ni][1]);
                MMA16(acc[mi][ni], ah0, ah1, ah2, ah3, bh[ni][0], bh[ni][1]);
            }
        }
    }

    // epilogue
#pragma unroll
    for (int mi = 0; mi < 4; mi++) {
        const int r0 = bm + wm * 64 + mi * 16 + qd;
#pragma unroll
        for (int ni = 0; ni < 4; ni++) {
            const int c0 = bn + wn * 32 + ni * 8 + tg * 2;
            const float b0 = bias ? bias[c0]     : 0.f;
            const float b1 = bias ? bias[c0 + 1] : 0.f;
            if (r0 < M)
                *(float2*)(C + (size_t)r0 * N + c0) =
                    make_float2(acc[mi][ni][0] + b0, acc[mi][ni][1] + b1);
            if (r0 + 8 < M)
                *(float2*)(C + (size_t)(r0 + 8) * N + c0) =
                    make_float2(acc[mi][ni][2] + b0, acc[mi][ni][3] + b1);
        }
    }
}

// ---------------- split: fp32 -> (hi, lo) fp16 --------------------------------
__global__ void split_f16(const float4* __restrict__ src, __half2* __restrict__ dh,
                          __half2* __restrict__ dl, int n4) {
    int i = blockIdx.x * blockDim.x + threadIdx.x;
    if (i < n4) {
        float4 v = src[i];
        __half2 h0 = __floats2half2_rn(v.x, v.y);
        __half2 h1 = __floats2half2_rn(v.z, v.w);
        float2 f0 = __half22float2(h0);
        float2 f1 = __half22float2(h1);
        dh[i * 2]     = h0;
        dh[i * 2 + 1] = h1;
        dl[i * 2]     = __floats2half2_rn(v.x - f0.x, v.y - f0.y);
        dl[i * 2 + 1] = __floats2half2_rn(v.z - f1.x, v.w - f1.y);
    }
}

// ---------------- h2 = relu(a+b), emitted directly as fp16 split --------------
__global__ void addrelu_split(const float4* __restrict__ a, const float4* __restrict__ b,
                              __half2* __restrict__ dh, __half2* __restrict__ dl, int n4) {
    int i = blockIdx.x * blockDim.x + threadIdx.x;
    if (i < n4) {
        float4 x = a[i], y = b[i];
        float4 v;
        v.x = fmaxf(x.x + y.x, 0.f); v.y = fmaxf(x.y + y.y, 0.f);
        v.z = fmaxf(x.z + y.z, 0.f); v.w = fmaxf(x.w + y.w, 0.f);
        __half2 h0 = __floats2half2_rn(v.x, v.y);
        __half2 h1 = __floats2half2_rn(v.z, v.w);
        float2 f0 = __half22float2(h0);
        float2 f1 = __half22float2(h1);
        dh[i * 2]     = h0;
        dh[i * 2 + 1] = h1;
        dl[i * 2]     = __floats2half2_rn(v.x - f0.x, v.y - f0.y);
        dl[i * 2 + 1] = __floats2half2_rn(v.z - f1.x, v.w - f1.y);
    }
}

// ---------------- final: c = relu(a+b) fp32 -----------------------------------
__global__ void add_relu4(const float4* __restrict__ a, const float4* __restrict__ b,
                          float4* __restrict__ c, int n4) {
    int i = blockIdx.x * blockDim.x + threadIdx.x;
    if (i < n4) {
        float4 x = a[i], y = b[i];
        float4 r;
        r.x = fmaxf(x.x + y.x, 0.f); r.y = fmaxf(x.y + y.y, 0.f);
        r.z = fmaxf(x.z + y.z, 0.f); r.w = fmaxf(x.w + y.w, 0.f);
        c[i] = r;
    }
}

// ---------------- bias for fused k|P GEMM: [k_b, zeros] -----------------------
__global__ void build_bias_kp(const float* __restrict__ kb, float* __restrict__ dst) {
    int i = blockIdx.x * blockDim.x + threadIdx.x;
    if (i < 2048) dst[i] = (i < 1024) ? kb[i] : 0.f;
}

// ---------------- pos weights: w[n][g][m] = max(relu(pe.pw+b), 1e-6) (NO log) --
__global__ __launch_bounds__(256)
void pos_logits(const float* __restrict__ pos_emb, const float* __restrict__ pw,
                const float* __restrict__ pb, float* __restrict__ Wt) {
    const int n  = blockIdx.y;
    const int m0 = blockIdx.x * 32;
    __shared__ float pe[32][65];
    __shared__ float pws[16][65];
    __shared__ float pbs[16];
    const int tid = threadIdx.x;

    if (tid < 16) pbs[tid] = pb[tid];
    {
        int gg = tid >> 4, c = (tid & 15) * 4;
        float4 v = *(const float4*)(pw + gg * 64 + c);
        pws[gg][c + 0] = v.x; pws[gg][c + 1] = v.y;
        pws[gg][c + 2] = v.z; pws[gg][c + 3] = v.w;
    }
    {
        int r = tid >> 4;
        int c = (tid & 15) * 4;
#pragma unroll
        for (int rr = 0; rr < 2; rr++) {
            int rw = r + rr * 16;
            int m = m0 + rw;
            float4 v = make_float4(0.f, 0.f, 0.f, 0.f);
            if (m < NONGT) v = *(const float4*)(pos_emb + ((size_t)n * NONGT + m) * EMB + c);
            pe[rw][c + 0] = v.x; pe[rw][c + 1] = v.y;
            pe[rw][c + 2] = v.z; pe[rw][c + 3] = v.w;
        }
    }
    __syncthreads();

    const int w = tid >> 5, lane = tid & 31;
    const int m = m0 + lane;
    const int g0 = w * 2, g1 = w * 2 + 1;
    float acc0 = pbs[g0], acc1 = pbs[g1];
#pragma unroll
    for (int e = 0; e < 64; e++) {
        float p = pe[lane][e];
        acc0 = fmaf(p, pws[g0][e], acc0);
        acc1 = fmaf(p, pws[g1][e], acc1);
    }
    if (m < NONGT) {
        Wt[(size_t)n * GW_STRIDE + g0 * NONGT + m] = fmaxf(acc0, 1e-6f);
        Wt[(size_t)n * GW_STRIDE + g1 * NONGT + m] = fmaxf(acc1, 1e-6f);
    }
}

// ---------------- aff: Aff[n][g][m] = 0.125 * q[n,g,:]·k[m,g,:] (pure store) --
__global__ __launch_bounds__(256)
void aff_add(const float* __restrict__ Q, const float* __restrict__ Kt, int ldk,
             float* __restrict__ Aff) {
    const int g  = blockIdx.z;
    const int n0 = blockIdx.y * 64;
    const int m0 = blockIdx.x * 64;
    __shared__ float qs[64][68];
    __shared__ float ks[64][68];
    const int tid = threadIdx.x;
    const int row = tid >> 2;
    const int c0  = tid & 3;

    const float* qbase = Q + (size_t)(n0 + row) * FEAT + g * DG;
#pragma unroll
    for (int i = 0; i < 4; i++) {
        int d = (c0 + 4 * i) * 4;
        float4 v = *(const float4*)(qbase + d);
        qs[d + 0][row] = v.x; qs[d + 1][row] = v.y;
        qs[d + 2][row] = v.z; qs[d + 3][row] = v.w;
    }
    const int mrow = m0 + row;
#pragma unroll
    for (int i = 0; i < 4; i++) {
        int d = (c0 + 4 * i) * 4;
        float4 v = make_float4(0.f, 0.f, 0.f, 0.f);
        if (mrow < NONGT) v = *(const float4*)(Kt + (size_t)mrow * ldk + g * DG + d);
        ks[d + 0][row] = v.x; ks[d + 1][row] = v.y;
        ks[d + 2][row] = v.z; ks[d + 3][row] = v.w;
    }
    __syncthreads();

    const int tx = tid & 15, ty = tid >> 4;
    float acc[4][4];
#pragma unroll
    for (int i = 0; i < 4; i++)
#pragma unroll
        for (int j = 0; j < 4; j++) acc[i][j] = 0.f;
#pragma unroll
    for (int d = 0; d < 64; d++) {
        float a[4], b[4];
        *(float4*)a = *(const float4*)&qs[d][ty * 4];
        *(float4*)b = *(const float4*)&ks[d][tx * 4];
#pragma unroll
        for (int i = 0; i < 4; i++)
#pragma unroll
            for (int j = 0; j < 4; j++) acc[i][j] = fmaf(a[i], b[j], acc[i][j]);
    }

#pragma unroll
    for (int i = 0; i < 4; i++) {
        int n = n0 + ty * 4 + i;
        float* arow = Aff + (size_t)n * GW_STRIDE + g * NONGT;
#pragma unroll
        for (int j = 0; j < 4; j++) {
            int m = m0 + tx * 4 + j;
            if (m < NONGT) arow[m] = 0.125f * acc[i][j];
        }
    }
}

// ---------------- softmax(w * e^aff) over m + out = s @ P_g + out_b ----------
__global__ __launch_bounds__(256)
void softmax_pv(const float* __restrict__ Wt, const float* __restrict__ Aff,
                const float* __restrict__ P, int ldp,
                const float* __restrict__ ob, float* __restrict__ Att) {
    const int g  = blockIdx.y;
    const int n0 = blockIdx.x * 16;
    __shared__ float s[16][301];
    const int tid = threadIdx.x, w = tid >> 5, lane = tid & 31;

#pragma unroll
    for (int rr = 0; rr < 2; rr++) {
        int r = w * 2 + rr;
        const float* srcW = Wt  + (size_t)(n0 + r) * GW_STRIDE + g * NONGT;
        const float* srcA = Aff + (size_t)(n0 + r) * GW_STRIDE + g * NONGT;
        float a[10], wv[10];
        float mx = -1e30f;
#pragma unroll
        for (int i = 0; i < 10; i++) {
            int m = lane + 32 * i;
            a[i]  = (m < NONGT) ? srcA[m] : -1e30f;
            wv[i] = (m < NONGT) ? srcW[m] : 0.f;
            mx = fmaxf(mx, a[i]);
        }
#pragma unroll
        for (int off = 16; off; off >>= 1) mx = fmaxf(mx, __shfl_xor_sync(~0u, mx, off));
        float sum = 0.f;
#pragma unroll
        for (int i = 0; i < 10; i++) {
            float e = wv[i] * __expf(a[i] - mx);
            a[i] = e;
            sum += e;
        }
#pragma unroll
        for (int off = 16; off; off >>= 1) sum += __shfl_xor_sync(~0u, sum, off);
        float inv = 1.f / sum;
#pragma unroll
        for (int i = 0; i < 10; i++) {
            int m = lane + 32 * i;
            if (m < NONGT) s[r][m] = a[i] * inv;
        }
    }
    __syncthreads();

    const int o = tid & 63, grp = tid >> 6;
    float acc0 = 0.f, acc1 = 0.f, acc2 = 0.f, acc3 = 0.f;
    const float* pcol = P + g * DG + o;
#pragma unroll 4
    for (int m = 0; m < NONGT; m++) {
        float p = __ldg(pcol + (size_t)m * ldp);
        acc0 = fmaf(s[grp][m],      p, acc0);
        acc1 = fmaf(s[grp + 4][m],  p, acc1);
        acc2 = fmaf(s[grp + 8][m],  p, acc2);
        acc3 = fmaf(s[grp + 12][m], p, acc3);
    }
    float b = ob[g * DG + o];
    Att[(size_t)(n0 + grp)      * FEAT + g * DG + o] = acc0 + b;
    Att[(size_t)(n0 + grp + 4)  * FEAT + g * DG + o] = acc1 + b;
    Att[(size_t)(n0 + grp + 8)  * FEAT + g * DG + o] = acc2 + b;
    Att[(size_t)(n0 + grp + 12) * FEAT + g * DG + o] = acc3 + b;
}

// ---------------- host-side helpers -------------------------------------------
static inline void split_launch(const float* src, __half* dh, __half* dl, int n) {
    int n4 = n / 4;
    split_f16<<<(n4 + 255) / 256, 256>>>((const float4*)src, (__half2*)dh, (__half2*)dl, n4);
}
static inline void gemm_launch(const __half* ah, const __half* al,
                               const __half* wh, const __half* wl,
                               const float* bias, float* c, int M, int N, int K) {
    dim3 grid(N / 128, (M + 127) / 128);
    gemm_lm<<<grid, 256, GSMEM>>>(ah, al, wh, wl, bias, c, M, N, K);
}

extern "C" void kernel_launch(void* const* d_in, const int* in_sizes, int n_in,
                              void* d_out, int out_size) {
    const float* x       = (const float*)d_in[0];
    const float* pos_emb = (const float*)d_in[1];
    const float* fc6_w   = (const float*)d_in[2];
    const float* fc6_b   = (const float*)d_in[3];
    const float* fc7_w   = (const float*)d_in[4];
    const float* fc7_b   = (const float*)d_in[5];
    const float* a1[8];
    const float* a2[8];
    for (int i = 0; i < 8; i++) a1[i] = (const float*)d_in[6 + i];
    for (int i = 0; i < 8; i++) a2[i] = (const float*)d_in[14 + i];
    // per block: pos_w, pos_b, q_w, q_b, k_w, k_b, out_w, out_b

    cudaFuncSetAttribute(gemm_lm, cudaFuncAttributeMaxDynamicSharedMemorySize, GSMEM);

    float *p_h, *p_h2, *p_q, *p_att, *p_kp, *p_w, *p_aff, *p_bkp;
    cudaGetSymbolAddress((void**)&p_h,   g_h);
    cudaGetSymbolAddress((void**)&p_h2,  g_h2);
    cudaGetSymbolAddress((void**)&p_q,   g_q);
    cudaGetSymbolAddress((void**)&p_att, g_att);
    cudaGetSymbolAddress((void**)&p_kp,  g_kp);
    cudaGetSymbolAddress((void**)&p_w,   g_w);
    cudaGetSymbolAddress((void**)&p_aff, g_aff);
    cudaGetSymbolAddress((void**)&p_bkp, g_bkp);

    __half *xh, *xl, *w6h, *w6l, *w7h, *w7l, *qwh, *qwl, *kpwh, *kpwl, *ahh, *all;
    cudaGetSymbolAddress((void**)&xh,   g_xh);
    cudaGetSymbolAddress((void**)&xl,   g_xl);
    cudaGetSymbolAddress((void**)&w6h,  g_w6h);
    cudaGetSymbolAddress((void**)&w6l,  g_w6l);
    cudaGetSymbolAddress((void**)&w7h,  g_w7h);
    cudaGetSymbolAddress((void**)&w7l,  g_w7l);
    cudaGetSymbolAddress((void**)&qwh,  g_qwh);
    cudaGetSymbolAddress((void**)&qwl,  g_qwl);
    cudaGetSymbolAddress((void**)&kpwh, g_kpwh);
    cudaGetSymbolAddress((void**)&kpwl, g_kpwl);
    cudaGetSymbolAddress((void**)&ahh,  g_ah);
    cudaGetSymbolAddress((void**)&all,  g_al);

    const int n4 = NTOK * FEAT / 4;

    // ---- fc6 ----
    split_launch(x,     xh,  xl,  NTOK * IN_CH);
    split_launch(fc6_w, w6h, w6l, FEAT * IN_CH);
    split_launch(fc7_w, w7h, w7l, FEAT * FEAT);
    gemm_launch(xh, xl, w6h, w6l, fc6_b, p_h, NTOK, FEAT, IN_CH);

    // ---- attention 1 ----
    split_launch(p_h, ahh, all, NTOK * FEAT);
    split_launch(a1[2], qwh, qwl, FEAT * FEAT);
    split_launch(a1[4], kpwh, kpwl, FEAT * FEAT);
    split_launch(a1[6], kpwh + 1024 * FEAT, kpwl + 1024 * FEAT, FEAT * FEAT);
    build_bias_kp<<<8, 256>>>(a1[5], p_bkp);

    gemm_launch(ahh, all, qwh, qwl, a1[3], p_q, NTOK, FEAT, FEAT);
    gemm_launch(ahh, all, kpwh, kpwl, p_bkp, p_kp, NONGT, 2048, FEAT);
    pos_logits<<<dim3((NONGT + 31) / 32, NTOK), 256>>>(pos_emb, a1[0], a1[1], p_w);
    aff_add<<<dim3((NONGT + 63) / 64, NTOK / 64, G), 256>>>(p_q, p_kp, 2048, p_aff);
    softmax_pv<<<dim3(NTOK / 16, G), 256>>>(p_w, p_aff, p_kp + 1024, 2048, a1[7], p_att);

    // ---- h2 = relu(h + att1), split for fc7 ----
    addrelu_split<<<(n4 + 255) / 256, 256>>>((const float4*)p_h, (const float4*)p_att,
                                             (__half2*)ahh, (__half2*)all, n4);

    // ---- fc7 ----
    gemm_launch(ahh, all, w7h, w7l, fc7_b, p_h2, NTOK, FEAT, FEAT);

    // ---- attention 2 ----
    split_launch(p_h2, ahh, all, NTOK * FEAT);
    split_launch(a2[2], qwh, qwl, FEAT * FEAT);
    split_launch(a2[4], kpwh, kpwl, FEAT * FEAT);
    split_launch(a2[6], kpwh + 1024 * FEAT, kpwl + 1024 * FEAT, FEAT * FEAT);
    build_bias_kp<<<8, 256>>>(a2[5], p_bkp);

    gemm_launch(ahh, all, qwh, qwl, a2[3], p_q, NTOK, FEAT, FEAT);
    gemm_launch(ahh, all, kpwh, kpwl, p_bkp, p_kp, NONGT, 2048, FEAT);
    pos_logits<<<dim3((NONGT + 31) / 32, NTOK), 256>>>(pos_emb, a2[0], a2[1], p_w);
    aff_add<<<dim3((NONGT + 63) / 64, NTOK / 64, G), 256>>>(p_q, p_kp, 2048, p_aff);
    softmax_pv<<<dim3(NTOK / 16, G), 256>>>(p_w, p_aff, p_kp + 1024, 2048, a2[7], p_att);

    // ---- out = relu(h2 + att2) ----
    add_relu4<<<(n4 + 255) / 256, 256>>>((const float4*)p_h2, (const float4*)p_att,
                                         (float4*)d_out, n4);
}

// round 10
// speedup vs baseline: 2.1028x; 1.0423x over previous
#include <cuda_runtime.h>
#include <cuda_fp16.h>
#include <math.h>
#include <stdint.h>

#define NTOK   2048
#define FEAT   1024
#define IN_CH  12544
#define NONGT  300
#define G      16
#define DG     64
#define EMB    64
#define GW_STRIDE (G * NONGT)   // 4800

// GEMM tile config: 128x128 CTA tile, BK=16, 512 threads, ldmatrix, 4-stage cp.async
#define ROWB   48                // smem row stride bytes (16 halves in first 32B)
#define TILEB  (128 * ROWB)      // 6144 B per operand tile
#define STGB   (4 * TILEB)       // Ah | Al | Bh | Bl = 24576 B
#define GSMEM  (4 * STGB)        // 4 stages = 98304 B

// ---------------- fp32 scratch ----------------
__device__ float g_h   [NTOK * FEAT];
__device__ float g_h2  [NTOK * FEAT];
__device__ float g_q   [NTOK * FEAT];
__device__ float g_att [NTOK * FEAT];
__device__ float g_kp  [384 * 2048];
__device__ float g_w1  [NTOK * G * NONGT];     // pos weights layer 1 (clamped)
__device__ float g_w2  [NTOK * G * NONGT];     // pos weights layer 2 (clamped)
__device__ float g_aff [NTOK * G * NONGT];     // q.k affinities
__device__ float g_bkp [2048];

// ---------------- fp16 split scratch ----------------
__device__ __half g_xh [NTOK * IN_CH];
__device__ __half g_xl [NTOK * IN_CH];
__device__ __half g_w6h[FEAT * IN_CH];
__device__ __half g_w6l[FEAT * IN_CH];
__device__ __half g_w7h[FEAT * FEAT];
__device__ __half g_w7l[FEAT * FEAT];
__device__ __half g_qwh[FEAT * FEAT];
__device__ __half g_qwl[FEAT * FEAT];
__device__ __half g_kpwh[2048 * FEAT];
__device__ __half g_kpwl[2048 * FEAT];
__device__ __half g_ah [NTOK * FEAT];
__device__ __half g_al [NTOK * FEAT];

// ---------------- helpers ----------------
__device__ __forceinline__ uint32_t cvta_s(const void* p) {
    return (uint32_t)__cvta_generic_to_shared(p);
}
__device__ __forceinline__ void cp16(uint32_t s, const void* g) {
    asm volatile("cp.async.cg.shared.global [%0], [%1], 16;\n" :: "r"(s), "l"(g));
}
#define LDSM_X4(r0, r1, r2, r3, a)                                              \
    asm volatile("ldmatrix.sync.aligned.m8n8.x4.shared.b16 {%0,%1,%2,%3}, [%4];" \
                 : "=r"(r0), "=r"(r1), "=r"(r2), "=r"(r3) : "r"(a))
#define MMA16(ACC, A0, A1, A2, A3, B0, B1)                                      \
    asm volatile(                                                               \
        "mma.sync.aligned.m16n8k16.row.col.f32.f16.f16.f32 "                    \
        "{%0,%1,%2,%3}, {%4,%5,%6,%7}, {%8,%9}, {%0,%1,%2,%3};\n"               \
        : "+f"(ACC[0]), "+f"(ACC[1]), "+f"(ACC[2]), "+f"(ACC[3])                \
        : "r"(A0), "r"(A1), "r"(A2), "r"(A3), "r"(B0), "r"(B1))

// ---------------- fp16x3 GEMM, 512 threads: C = A[M,K] @ W[N,K]^T (+bias) ----
// A,W pre-split (hi,lo) fp16. K % 16 == 0, N % 128 == 0. A readable up to row
// ceil(M/128)*128-1 (scratch buffers satisfy this).
__global__ __launch_bounds__(512, 1)
void gemm_lm(const __half* __restrict__ Ah, const __half* __restrict__ Al,
             const __half* __restrict__ Wh, const __half* __restrict__ Wl,
             const float* __restrict__ bias, float* __restrict__ C,
             int M, int N, int K) {
    extern __shared__ char dsm[];
    const uint32_t sbase = cvta_s(dsm);

    const int tid  = threadIdx.x;
    const int lane = tid & 31;
    const int wid  = tid >> 5;       // 0..15
    const int wm   = wid >> 2;       // 0..3
    const int wn   = wid & 3;        // 0..3
    const int qd   = lane >> 2;
    const int tg   = lane & 3;
    const int bm   = blockIdx.y * 128;
    const int bn   = blockIdx.x * 128;

    // cp.async: tid<256 -> A tiles (hi+lo), tid>=256 -> B tiles (hi+lo)
    const int lrow = (tid & 255) >> 1;
    const int lch  = tid & 1;
    const bool isA = tid < 256;
    const __half* gH = (isA ? Ah + (size_t)(bm + lrow) * K
                            : Wh + (size_t)(bn + lrow) * K) + lch * 8;
    const __half* gL = (isA ? Al + (size_t)(bm + lrow) * K
                            : Wl + (size_t)(bn + lrow) * K) + lch * 8;
    const uint32_t woffH = (uint32_t)((isA ? 0 : 2 * TILEB) + lrow * ROWB + lch * 16);

    // ldmatrix lane addressing
    const uint32_t aRow  = (uint32_t)(wm * 32 + (lane & 7) + ((lane >> 3) & 1) * 8);
    const uint32_t aByte = (uint32_t)(((lane >> 4) & 1) * 16);
    const uint32_t bRow  = (uint32_t)(wn * 32 + ((lane >> 4) & 1) * 8 + (lane & 7));
    const uint32_t bByte = (uint32_t)(((lane >> 3) & 1) * 16);

    float acc[2][4][4];
#pragma unroll
    for (int i = 0; i < 2; i++)
#pragma unroll
        for (int j = 0; j < 4; j++)
#pragma unroll
            for (int r = 0; r < 4; r++) acc[i][j][r] = 0.f;

    const int nk = K / 16;

    auto load_stage = [&](int kt) {
        const uint32_t st = sbase + (uint32_t)(kt & 3) * STGB;
        const size_t k0 = (size_t)kt * 16;
        cp16(st + woffH, gH + k0);
        cp16(st + TILEB + woffH, gL + k0);
    };

    // prologue: stages 0..2
#pragma unroll
    for (int s = 0; s < 3; s++) {
        if (s < nk) load_stage(s);
        asm volatile("cp.async.commit_group;\n");
    }

    for (int kt = 0; kt < nk; kt++) {
        asm volatile("cp.async.wait_group 2;\n");
        __syncthreads();
        if (kt + 3 < nk) load_stage(kt + 3);
        asm volatile("cp.async.commit_group;\n");

        const uint32_t st = sbase + (uint32_t)(kt & 3) * STGB;

        // ---- load ALL fragments for this k-tile ----
        uint32_t ah[2][4], al_[2][4], bh[4][2], bl[4][2];
#pragma unroll
        for (int mi = 0; mi < 2; mi++) {
            const uint32_t ar = (aRow + mi * 16) * ROWB + aByte;
            LDSM_X4(ah[mi][0], ah[mi][1], ah[mi][2], ah[mi][3], st + ar);
            LDSM_X4(al_[mi][0], al_[mi][1], al_[mi][2], al_[mi][3], st + TILEB + ar);
        }
        {
            const uint32_t br = bRow * ROWB + bByte;
            uint32_t r0, r1, r2, r3;
            LDSM_X4(r0, r1, r2, r3, st + 2 * TILEB + br);
            bh[0][0] = r0; bh[0][1] = r1; bh[1][0] = r2; bh[1][1] = r3;
            LDSM_X4(r0, r1, r2, r3, st + 2 * TILEB + br + 16 * ROWB);
            bh[2][0] = r0; bh[2][1] = r1; bh[3][0] = r2; bh[3][1] = r3;
            LDSM_X4(r0, r1, r2, r3, st + 3 * TILEB + br);
            bl[0][0] = r0; bl[0][1] = r1; bl[1][0] = r2; bl[1][1] = r3;
            LDSM_X4(r0, r1, r2, r3, st + 3 * TILEB + br + 16 * ROWB);
            bl[2][0] = r0; bl[2][1] = r1; bl[3][0] = r2; bl[3][1] = r3;
        }

        // ---- term-major MMA issue: accumulator reuse distance = 8 ----
#pragma unroll
        for (int mi = 0; mi < 2; mi++)
#pragma unroll
            for (int ni = 0; ni < 4; ni++)
                MMA16(acc[mi][ni], al_[mi][0], al_[mi][1], al_[mi][2], al_[mi][3],
                      bh[ni][0], bh[ni][1]);
#pragma unroll
        for (int mi = 0; mi < 2; mi++)
#pragma unroll
            for (int ni = 0; ni < 4; ni++)
                MMA16(acc[mi][ni], ah[mi][0], ah[mi][1], ah[mi][2], ah[mi][3],
                      bl[ni][0], bl[ni][1]);
#pragma unroll
        for (int mi = 0; mi < 2; mi++)
#pragma unroll
            for (int ni = 0; ni < 4; ni++)
                MMA16(acc[mi][ni], ah[mi][0], ah[mi][1], ah[mi][2], ah[mi][3],
                      bh[ni][0], bh[ni][1]);
    }

    // epilogue
#pragma unroll
    for (int mi = 0; mi < 2; mi++) {
        const int r0 = bm + wm * 32 + mi * 16 + qd;
#pragma unroll
        for (int ni = 0; ni < 4; ni++) {
            const int c0 = bn + wn * 32 + ni * 8 + tg * 2;
            const float b0 = bias ? bias[c0]     : 0.f;
            const float b1 = bias ? bias[c0 + 1] : 0.f;
            if (r0 < M)
                *(float2*)(C + (size_t)r0 * N + c0) =
                    make_float2(acc[mi][ni][0] + b0, acc[mi][ni][1] + b1);
            if (r0 + 8 < M)
                *(float2*)(C + (size_t)(r0 + 8) * N + c0) =
                    make_float2(acc[mi][ni][2] + b0, acc[mi][ni][3] + b1);
        }
    }
}

// ---------------- split: fp32 -> (hi, lo) fp16 --------------------------------
__global__ void split_f16(const float4* __restrict__ src, __half2* __restrict__ dh,
                          __half2* __restrict__ dl, int n4) {
    int i = blockIdx.x * blockDim.x + threadIdx.x;
    if (i < n4) {
        float4 v = src[i];
        __half2 h0 = __floats2half2_rn(v.x, v.y);
        __half2 h1 = __floats2half2_rn(v.z, v.w);
        float2 f0 = __half22float2(h0);
        float2 f1 = __half22float2(h1);
        dh[i * 2]     = h0;
        dh[i * 2 + 1] = h1;
        dl[i * 2]     = __floats2half2_rn(v.x - f0.x, v.y - f0.y);
        dl[i * 2 + 1] = __floats2half2_rn(v.z - f1.x, v.w - f1.y);
    }
}

// ---------------- h2 = relu(a+b), emitted directly as fp16 split --------------
__global__ void addrelu_split(const float4* __restrict__ a, const float4* __restrict__ b,
                              __half2* __restrict__ dh, __half2* __restrict__ dl, int n4) {
    int i = blockIdx.x * blockDim.x + threadIdx.x;
    if (i < n4) {
        float4 x = a[i], y = b[i];
        float4 v;
        v.x = fmaxf(x.x + y.x, 0.f); v.y = fmaxf(x.y + y.y, 0.f);
        v.z = fmaxf(x.z + y.z, 0.f); v.w = fmaxf(x.w + y.w, 0.f);
        __half2 h0 = __floats2half2_rn(v.x, v.y);
        __half2 h1 = __floats2half2_rn(v.z, v.w);
        float2 f0 = __half22float2(h0);
        float2 f1 = __half22float2(h1);
        dh[i * 2]     = h0;
        dh[i * 2 + 1] = h1;
        dl[i * 2]     = __floats2half2_rn(v.x - f0.x, v.y - f0.y);
        dl[i * 2 + 1] = __floats2half2_rn(v.z - f1.x, v.w - f1.y);
    }
}

// ---------------- final: c = relu(a+b) fp32 -----------------------------------
__global__ void add_relu4(const float4* __restrict__ a, const float4* __restrict__ b,
                          float4* __restrict__ c, int n4) {
    int i = blockIdx.x * blockDim.x + threadIdx.x;
    if (i < n4) {
        float4 x = a[i], y = b[i];
        float4 r;
        r.x = fmaxf(x.x + y.x, 0.f); r.y = fmaxf(x.y + y.y, 0.f);
        r.z = fmaxf(x.z + y.z, 0.f); r.w = fmaxf(x.w + y.w, 0.f);
        c[i] = r;
    }
}

// ---------------- bias for fused k|P GEMM: [k_b, zeros] -----------------------
__global__ void build_bias_kp(const float* __restrict__ kb, float* __restrict__ dst) {
    int i = blockIdx.x * blockDim.x + threadIdx.x;
    if (i < 2048) dst[i] = (i < 1024) ? kb[i] : 0.f;
}

// ---------------- dual pos weights: both layers in one pos_emb pass -----------
// W{1,2}[n][g][m] = max(relu(pos_emb[n,m]·pw{1,2}[g] + pb{1,2}[g]), 1e-6)
__global__ __launch_bounds__(256)
void pos_logits_dual(const float* __restrict__ pos_emb,
                     const float* __restrict__ pw1, const float* __restrict__ pb1,
                     const float* __restrict__ pw2, const float* __restrict__ pb2,
                     float* __restrict__ W1, float* __restrict__ W2) {
    const int n  = blockIdx.y;
    const int m0 = blockIdx.x * 32;
    __shared__ float pe[32][65];
    __shared__ float pws[32][65];   // rows 0..15: layer1, 16..31: layer2
    __shared__ float pbs[32];
    const int tid = threadIdx.x;

    if (tid < 16) pbs[tid] = pb1[tid];
    else if (tid < 32) pbs[tid] = pb2[tid - 16];
    {   // 32 weight rows x 64: each thread loads 8 floats
        int row = tid >> 3;
        int c = (tid & 7) * 8;
        const float* src = (row < 16) ? pw1 + row * 64 + c : pw2 + (row - 16) * 64 + c;
        float4 v0 = *(const float4*)src;
        float4 v1 = *(const float4*)(src + 4);
        pws[row][c + 0] = v0.x; pws[row][c + 1] = v0.y;
        pws[row][c + 2] = v0.z; pws[row][c + 3] = v0.w;
        pws[row][c + 4] = v1.x; pws[row][c + 5] = v1.y;
        pws[row][c + 6] = v1.z; pws[row][c + 7] = v1.w;
    }
    {
        int r = tid >> 4;
        int c = (tid & 15) * 4;
#pragma unroll
        for (int rr = 0; rr < 2; rr++) {
            int rw = r + rr * 16;
            int m = m0 + rw;
            float4 v = make_float4(0.f, 0.f, 0.f, 0.f);
            if (m < NONGT) v = *(const float4*)(pos_emb + ((size_t)n * NONGT + m) * EMB + c);
            pe[rw][c + 0] = v.x; pe[rw][c + 1] = v.y;
            pe[rw][c + 2] = v.z; pe[rw][c + 3] = v.w;
        }
    }
    __syncthreads();

    const int w = tid >> 5, lane = tid & 31;
    const int m = m0 + lane;
    const int g0 = w * 2, g1 = w * 2 + 1;
    float a10 = pbs[g0], a11 = pbs[g1];
    float a20 = pbs[16 + g0], a21 = pbs[16 + g1];
#pragma unroll
    for (int e = 0; e < 64; e++) {
        float p = pe[lane][e];
        a10 = fmaf(p, pws[g0][e],      a10);
        a11 = fmaf(p, pws[g1][e],      a11);
        a20 = fmaf(p, pws[16 + g0][e], a20);
        a21 = fmaf(p, pws[16 + g1][e], a21);
    }
    if (m < NONGT) {
        const size_t base = (size_t)n * GW_STRIDE;
        W1[base + g0 * NONGT + m] = fmaxf(a10, 1e-6f);
        W1[base + g1 * NONGT + m] = fmaxf(a11, 1e-6f);
        W2[base + g0 * NONGT + m] = fmaxf(a20, 1e-6f);
        W2[base + g1 * NONGT + m] = fmaxf(a21, 1e-6f);
    }
}

// ---------------- aff: Aff[n][g][m] = 0.125 * q[n,g,:]·k[m,g,:] (pure store) --
__global__ __launch_bounds__(256)
void aff_add(const float* __restrict__ Q, const float* __restrict__ Kt, int ldk,
             float* __restrict__ Aff) {
    const int g  = blockIdx.z;
    const int n0 = blockIdx.y * 64;
    const int m0 = blockIdx.x * 64;
    __shared__ float qs[64][68];
    __shared__ float ks[64][68];
    const int tid = threadIdx.x;
    const int row = tid >> 2;
    const int c0  = tid & 3;

    const float* qbase = Q + (size_t)(n0 + row) * FEAT + g * DG;
#pragma unroll
    for (int i = 0; i < 4; i++) {
        int d = (c0 + 4 * i) * 4;
        float4 v = *(const float4*)(qbase + d);
        qs[d + 0][row] = v.x; qs[d + 1][row] = v.y;
        qs[d + 2][row] = v.z; qs[d + 3][row] = v.w;
    }
    const int mrow = m0 + row;
#pragma unroll
    for (int i = 0; i < 4; i++) {
        int d = (c0 + 4 * i) * 4;
        float4 v = make_float4(0.f, 0.f, 0.f, 0.f);
        if (mrow < NONGT) v = *(const float4*)(Kt + (size_t)mrow * ldk + g * DG + d);
        ks[d + 0][row] = v.x; ks[d + 1][row] = v.y;
        ks[d + 2][row] = v.z; ks[d + 3][row] = v.w;
    }
    __syncthreads();

    const int tx = tid & 15, ty = tid >> 4;
    float acc[4][4];
#pragma unroll
    for (int i = 0; i < 4; i++)
#pragma unroll
        for (int j = 0; j < 4; j++) acc[i][j] = 0.f;
#pragma unroll
    for (int d = 0; d < 64; d++) {
        float a[4], b[4];
        *(float4*)a = *(const float4*)&qs[d][ty * 4];
        *(float4*)b = *(const float4*)&ks[d][tx * 4];
#pragma unroll
        for (int i = 0; i < 4; i++)
#pragma unroll
            for (int j = 0; j < 4; j++) acc[i][j] = fmaf(a[i], b[j], acc[i][j]);
    }

#pragma unroll
    for (int i = 0; i < 4; i++) {
        int n = n0 + ty * 4 + i;
        float* arow = Aff + (size_t)n * GW_STRIDE + g * NONGT;
#pragma unroll
        for (int j = 0; j < 4; j++) {
            int m = m0 + tx * 4 + j;
            if (m < NONGT) arow[m] = 0.125f * acc[i][j];
        }
    }
}

// ---------------- softmax(w * e^aff) over m + out = s @ P_g + out_b ----------
__global__ __launch_bounds__(256)
void softmax_pv(const float* __restrict__ Wt, const float* __restrict__ Aff,
                const float* __restrict__ P, int ldp,
                const float* __restrict__ ob, float* __restrict__ Att) {
    const int g  = blockIdx.y;
    const int n0 = blockIdx.x * 16;
    __shared__ float s[16][301];
    const int tid = threadIdx.x, w = tid >> 5, lane = tid & 31;

#pragma unroll
    for (int rr = 0; rr < 2; rr++) {
        int r = w * 2 + rr;
        const float* srcW = Wt  + (size_t)(n0 + r) * GW_STRIDE + g * NONGT;
        const float* srcA = Aff + (size_t)(n0 + r) * GW_STRIDE + g * NONGT;
        float a[10], wv[10];
        float mx = -1e30f;
#pragma unroll
        for (int i = 0; i < 10; i++) {
            int m = lane + 32 * i;
            a[i]  = (m < NONGT) ? srcA[m] : -1e30f;
            wv[i] = (m < NONGT) ? srcW[m] : 0.f;
            mx = fmaxf(mx, a[i]);
        }
#pragma unroll
        for (int off = 16; off; off >>= 1) mx = fmaxf(mx, __shfl_xor_sync(~0u, mx, off));
        float sum = 0.f;
#pragma unroll
        for (int i = 0; i < 10; i++) {
            float e = wv[i] * __expf(a[i] - mx);
            a[i] = e;
            sum += e;
        }
#pragma unroll
        for (int off = 16; off; off >>= 1) sum += __shfl_xor_sync(~0u, sum, off);
        float inv = 1.f / sum;
#pragma unroll
        for (int i = 0; i < 10; i++) {
            int m = lane + 32 * i;
            if (m < NONGT) s[r][m] = a[i] * inv;
        }
    }
    __syncthreads();

    const int o = tid & 63, grp = tid >> 6;
    float acc0 = 0.f, acc1 = 0.f, acc2 = 0.f, acc3 = 0.f;
    const float* pcol = P + g * DG + o;
#pragma unroll 4
    for (int m = 0; m < NONGT; m++) {
        float p = __ldg(pcol + (size_t)m * ldp);
        acc0 = fmaf(s[grp][m],      p, acc0);
        acc1 = fmaf(s[grp + 4][m],  p, acc1);
        acc2 = fmaf(s[grp + 8][m],  p, acc2);
        acc3 = fmaf(s[grp + 12][m], p, acc3);
    }
    float b = ob[g * DG + o];
    Att[(size_t)(n0 + grp)      * FEAT + g * DG + o] = acc0 + b;
    Att[(size_t)(n0 + grp + 4)  * FEAT + g * DG + o] = acc1 + b;
    Att[(size_t)(n0 + grp + 8)  * FEAT + g * DG + o] = acc2 + b;
    Att[(size_t)(n0 + grp + 12) * FEAT + g * DG + o] = acc3 + b;
}

// ---------------- host-side helpers -------------------------------------------
static inline void split_launch(const float* src, __half* dh, __half* dl, int n) {
    int n4 = n / 4;
    split_f16<<<(n4 + 255) / 256, 256>>>((const float4*)src, (__half2*)dh, (__half2*)dl, n4);
}
static inline void gemm_launch(const __half* ah, const __half* al,
                               const __half* wh, const __half* wl,
                               const float* bias, float* c, int M, int N, int K) {
    dim3 grid(N / 128, (M + 127) / 128);
    gemm_lm<<<grid, 512, GSMEM>>>(ah, al, wh, wl, bias, c, M, N, K);
}

extern "C" void kernel_launch(void* const* d_in, const int* in_sizes, int n_in,
                              void* d_out, int out_size) {
    const float* x       = (const float*)d_in[0];
    const float* pos_emb = (const float*)d_in[1];
    const float* fc6_w   = (const float*)d_in[2];
    const float* fc6_b   = (const float*)d_in[3];
    const float* fc7_w   = (const float*)d_in[4];
    const float* fc7_b   = (const float*)d_in[5];
    const float* a1[8];
    const float* a2[8];
    for (int i = 0; i < 8; i++) a1[i] = (const float*)d_in[6 + i];
    for (int i = 0; i < 8; i++) a2[i] = (const float*)d_in[14 + i];
    // per block: pos_w, pos_b, q_w, q_b, k_w, k_b, out_w, out_b

    cudaFuncSetAttribute(gemm_lm, cudaFuncAttributeMaxDynamicSharedMemorySize, GSMEM);

    float *p_h, *p_h2, *p_q, *p_att, *p_kp, *p_w1, *p_w2, *p_aff, *p_bkp;
    cudaGetSymbolAddress((void**)&p_h,   g_h);
    cudaGetSymbolAddress((void**)&p_h2,  g_h2);
    cudaGetSymbolAddress((void**)&p_q,   g_q);
    cudaGetSymbolAddress((void**)&p_att, g_att);
    cudaGetSymbolAddress((void**)&p_kp,  g_kp);
    cudaGetSymbolAddress((void**)&p_w1,  g_w1);
    cudaGetSymbolAddress((void**)&p_w2,  g_w2);
    cudaGetSymbolAddress((void**)&p_aff, g_aff);
    cudaGetSymbolAddress((void**)&p_bkp, g_bkp);

    __half *xh, *xl, *w6h, *w6l, *w7h, *w7l, *qwh, *qwl, *kpwh, *kpwl, *ahh, *all;
    cudaGetSymbolAddress((void**)&xh,   g_xh);
    cudaGetSymbolAddress((void**)&xl,   g_xl);
    cudaGetSymbolAddress((void**)&w6h,  g_w6h);
    cudaGetSymbolAddress((void**)&w6l,  g_w6l);
    cudaGetSymbolAddress((void**)&w7h,  g_w7h);
    cudaGetSymbolAddress((void**)&w7l,  g_w7l);
    cudaGetSymbolAddress((void**)&qwh,  g_qwh);
    cudaGetSymbolAddress((void**)&qwl,  g_qwl);
    cudaGetSymbolAddress((void**)&kpwh, g_kpwh);
    cudaGetSymbolAddress((void**)&kpwl, g_kpwl);
    cudaGetSymbolAddress((void**)&ahh,  g_ah);
    cudaGetSymbolAddress((void**)&all,  g_al);

    const int n4 = NTOK * FEAT / 4;

    // ---- fc6 + both pos-weight passes ----
    split_launch(x,     xh,  xl,  NTOK * IN_CH);
    split_launch(fc6_w, w6h, w6l, FEAT * IN_CH);
    split_launch(fc7_w, w7h, w7l, FEAT * FEAT);
    pos_logits_dual<<<dim3((NONGT + 31) / 32, NTOK), 256>>>(
        pos_emb, a1[0], a1[1], a2[0], a2[1], p_w1, p_w2);
    gemm_launch(xh, xl, w6h, w6l, fc6_b, p_h, NTOK, FEAT, IN_CH);

    // ---- attention 1 ----
    split_launch(p_h, ahh, all, NTOK * FEAT);
    split_launch(a1[2], qwh, qwl, FEAT * FEAT);
    split_launch(a1[4], kpwh, kpwl, FEAT * FEAT);
    split_launch(a1[6], kpwh + 1024 * FEAT, kpwl + 1024 * FEAT, FEAT * FEAT);
    build_bias_kp<<<8, 256>>>(a1[5], p_bkp);

    gemm_launch(ahh, all, qwh, qwl, a1[3], p_q, NTOK, FEAT, FEAT);
    gemm_launch(ahh, all, kpwh, kpwl, p_bkp, p_kp, NONGT, 2048, FEAT);
    aff_add<<<dim3((NONGT + 63) / 64, NTOK / 64, G), 256>>>(p_q, p_kp, 2048, p_aff);
    softmax_pv<<<dim3(NTOK / 16, G), 256>>>(p_w1, p_aff, p_kp + 1024, 2048, a1[7], p_att);

    // ---- h2 = relu(h + att1), split for fc7 ----
    addrelu_split<<<(n4 + 255) / 256, 256>>>((const float4*)p_h, (const float4*)p_att,
                                             (__half2*)ahh, (__half2*)all, n4);

    // ---- fc7 ----
    gemm_launch(ahh, all, w7h, w7l, fc7_b, p_h2, NTOK, FEAT, FEAT);

    // ---- attention 2 ----
    split_launch(p_h2, ahh, all, NTOK * FEAT);
    split_launch(a2[2], qwh, qwl, FEAT * FEAT);
    split_launch(a2[4], kpwh, kpwl, FEAT * FEAT);
    split_launch(a2[6], kpwh + 1024 * FEAT, kpwl + 1024 * FEAT, FEAT * FEAT);
    build_bias_kp<<<8, 256>>>(a2[5], p_bkp);

    gemm_launch(ahh, all, qwh, qwl, a2[3], p_q, NTOK, FEAT, FEAT);
    gemm_launch(ahh, all, kpwh, kpwl, p_bkp, p_kp, NONGT, 2048, FEAT);
    aff_add<<<dim3((NONGT + 63) / 64, NTOK / 64, G), 256>>>(p_q, p_kp, 2048, p_aff);
    softmax_pv<<<dim3(NTOK / 16, G), 256>>>(p_w2, p_aff, p_kp + 1024, 2048, a2[7], p_att);

    // ---- out = relu(h2 + att2) ----
    add_relu4<<<(n4 + 255) / 256, 256>>>((const float4*)p_h2, (const float4*)p_att,
                                         (float4*)d_out, n4);
}

// round 13
// speedup vs baseline: 2.1764x; 1.0350x over previous
#include <cuda_runtime.h>
#include <cuda_fp16.h>
#include <math.h>
#include <stdint.h>

#define NTOK   2048
#define FEAT   1024
#define IN_CH  12544
#define NONGT  300
#define G      16
#define DG     64
#define EMB    64
#define GW_STRIDE (G * NONGT)   // 4800

// GEMM tile config: 128x128 CTA tile, BK=16, 512 threads, ldmatrix, 4-stage cp.async
#define ROWB   48                // smem row stride bytes (16 halves in first 32B)
#define TILEB  (128 * ROWB)      // 6144 B per operand tile
#define STGB   (4 * TILEB)       // Ah | Al | Bh | Bl = 24576 B
#define GSMEM  (4 * STGB)        // 4 stages = 98304 B

// ---------------- fp32 scratch ----------------
__device__ float g_h   [NTOK * FEAT];
__device__ float g_h2  [NTOK * FEAT];
__device__ float g_q   [NTOK * FEAT];
__device__ float g_att [NTOK * FEAT];
__device__ float g_kp  [384 * 2048];
__device__ float g_w1  [NTOK * G * NONGT];     // pos weights layer 1 (clamped)
__device__ float g_w2  [NTOK * G * NONGT];     // pos weights layer 2 (clamped)
__device__ float g_aff [NTOK * G * NONGT];     // q.k affinities
__device__ float g_bkp [2048];

// ---------------- fp16 split scratch ----------------
__device__ __half g_xh [NTOK * IN_CH];
__device__ __half g_xl [NTOK * IN_CH];
__device__ __half g_w6h[FEAT * IN_CH];
__device__ __half g_w6l[FEAT * IN_CH];
__device__ __half g_w7h[FEAT * FEAT];
__device__ __half g_w7l[FEAT * FEAT];
__device__ __half g_qwh[FEAT * FEAT];
__device__ __half g_qwl[FEAT * FEAT];
__device__ __half g_kpwh[2048 * FEAT];
__device__ __half g_kpwl[2048 * FEAT];
__device__ __half g_ah [NTOK * FEAT];          // split buffer A (fc6 out / attn2 in)
__device__ __half g_al [NTOK * FEAT];
__device__ __half g_bh [NTOK * FEAT];          // split buffer B (fc7 in)
__device__ __half g_bl [NTOK * FEAT];

// ---------------- helpers ----------------
__device__ __forceinline__ uint32_t cvta_s(const void* p) {
    return (uint32_t)__cvta_generic_to_shared(p);
}
__device__ __forceinline__ void cp16(uint32_t s, const void* g) {
    asm volatile("cp.async.cg.shared.global [%0], [%1], 16;\n" :: "r"(s), "l"(g));
}
#define LDSM_X4(r0, r1, r2, r3, a)                                              \
    asm volatile("ldmatrix.sync.aligned.m8n8.x4.shared.b16 {%0,%1,%2,%3}, [%4];" \
                 : "=r"(r0), "=r"(r1), "=r"(r2), "=r"(r3) : "r"(a))
#define MMA16(ACC, A0, A1, A2, A3, B0, B1)                                      \
    asm volatile(                                                               \
        "mma.sync.aligned.m16n8k16.row.col.f32.f16.f16.f32 "                    \
        "{%0,%1,%2,%3}, {%4,%5,%6,%7}, {%8,%9}, {%0,%1,%2,%3};\n"               \
        : "+f"(ACC[0]), "+f"(ACC[1]), "+f"(ACC[2]), "+f"(ACC[3])                \
        : "r"(A0), "r"(A1), "r"(A2), "r"(A3), "r"(B0), "r"(B1))

// ---------------- fp16x3 GEMM, 512 threads: C = A[M,K] @ W[N,K]^T (+bias) ----
// Optional dH/dL: epilogue also emits the (hi,lo) fp16 split of C.
__global__ __launch_bounds__(512, 1)
void gemm_lm(const __half* __restrict__ Ah, const __half* __restrict__ Al,
             const __half* __restrict__ Wh, const __half* __restrict__ Wl,
             const float* __restrict__ bias, float* __restrict__ C,
             __half2* __restrict__ dH, __half2* __restrict__ dL,
             int M, int N, int K) {
    extern __shared__ char dsm[];
    const uint32_t sbase = cvta_s(dsm);

    const int tid  = threadIdx.x;
    const int lane = tid & 31;
    const int wid  = tid >> 5;       // 0..15
    const int wm   = wid >> 2;       // 0..3
    const int wn   = wid & 3;        // 0..3
    const int qd   = lane >> 2;
    const int tg   = lane & 3;
    const int bm   = blockIdx.y * 128;
    const int bn   = blockIdx.x * 128;

    // cp.async: tid<256 -> A tiles (hi+lo), tid>=256 -> B tiles (hi+lo)
    const int lrow = (tid & 255) >> 1;
    const int lch  = tid & 1;
    const bool isA = tid < 256;
    const __half* gH = (isA ? Ah + (size_t)(bm + lrow) * K
                            : Wh + (size_t)(bn + lrow) * K) + lch * 8;
    const __half* gL = (isA ? Al + (size_t)(bm + lrow) * K
                            : Wl + (size_t)(bn + lrow) * K) + lch * 8;
    const uint32_t woffH = (uint32_t)((isA ? 0 : 2 * TILEB) + lrow * ROWB + lch * 16);

    // ldmatrix lane addressing
    const uint32_t aRow  = (uint32_t)(wm * 32 + (lane & 7) + ((lane >> 3) & 1) * 8);
    const uint32_t aByte = (uint32_t)(((lane >> 4) & 1) * 16);
    const uint32_t bRow  = (uint32_t)(wn * 32 + ((lane >> 4) & 1) * 8 + (lane & 7));
    const uint32_t bByte = (uint32_t)(((lane >> 3) & 1) * 16);

    float acc[2][4][4];
#pragma unroll
    for (int i = 0; i < 2; i++)
#pragma unroll
        for (int j = 0; j < 4; j++)
#pragma unroll
            for (int r = 0; r < 4; r++) acc[i][j][r] = 0.f;

    const int nk = K / 16;

    auto load_stage = [&](int kt) {
        const uint32_t st = sbase + (uint32_t)(kt & 3) * STGB;
        const size_t k0 = (size_t)kt * 16;
        cp16(st + woffH, gH + k0);
        cp16(st + TILEB + woffH, gL + k0);
    };

#pragma unroll
    for (int s = 0; s < 3; s++) {
        if (s < nk) load_stage(s);
        asm volatile("cp.async.commit_group;\n");
    }

    for (int kt = 0; kt < nk; kt++) {
        asm volatile("cp.async.wait_group 2;\n");
        __syncthreads();
        if (kt + 3 < nk) load_stage(kt + 3);
        asm volatile("cp.async.commit_group;\n");

        const uint32_t st = sbase + (uint32_t)(kt & 3) * STGB;

        uint32_t ah[2][4], al_[2][4], bh[4][2], bl[4][2];
#pragma unroll
        for (int mi = 0; mi < 2; mi++) {
            const uint32_t ar = (aRow + mi * 16) * ROWB + aByte;
            LDSM_X4(ah[mi][0], ah[mi][1], ah[mi][2], ah[mi][3], st + ar);
            LDSM_X4(al_[mi][0], al_[mi][1], al_[mi][2], al_[mi][3], st + TILEB + ar);
        }
        {
            const uint32_t br = bRow * ROWB + bByte;
            uint32_t r0, r1, r2, r3;
            LDSM_X4(r0, r1, r2, r3, st + 2 * TILEB + br);
            bh[0][0] = r0; bh[0][1] = r1; bh[1][0] = r2; bh[1][1] = r3;
            LDSM_X4(r0, r1, r2, r3, st + 2 * TILEB + br + 16 * ROWB);
            bh[2][0] = r0; bh[2][1] = r1; bh[3][0] = r2; bh[3][1] = r3;
            LDSM_X4(r0, r1, r2, r3, st + 3 * TILEB + br);
            bl[0][0] = r0; bl[0][1] = r1; bl[1][0] = r2; bl[1][1] = r3;
            LDSM_X4(r0, r1, r2, r3, st + 3 * TILEB + br + 16 * ROWB);
            bl[2][0] = r0; bl[2][1] = r1; bl[3][0] = r2; bl[3][1] = r3;
        }

        // term-major MMA issue: accumulator reuse distance = 8
#pragma unroll
        for (int mi = 0; mi < 2; mi++)
#pragma unroll
            for (int ni = 0; ni < 4; ni++)
                MMA16(acc[mi][ni], al_[mi][0], al_[mi][1], al_[mi][2], al_[mi][3],
                      bh[ni][0], bh[ni][1]);
#pragma unroll
        for (int mi = 0; mi < 2; mi++)
#pragma unroll
            for (int ni = 0; ni < 4; ni++)
                MMA16(acc[mi][ni], ah[mi][0], ah[mi][1], ah[mi][2], ah[mi][3],
                      bl[ni][0], bl[ni][1]);
#pragma unroll
        for (int mi = 0; mi < 2; mi++)
#pragma unroll
            for (int ni = 0; ni < 4; ni++)
                MMA16(acc[mi][ni], ah[mi][0], ah[mi][1], ah[mi][2], ah[mi][3],
                      bh[ni][0], bh[ni][1]);
    }

    // epilogue (+ optional fused fp16 split)
#pragma unroll
    for (int mi = 0; mi < 2; mi++) {
        const int r0 = bm + wm * 32 + mi * 16 + qd;
#pragma unroll
        for (int ni = 0; ni < 4; ni++) {
            const int c0 = bn + wn * 32 + ni * 8 + tg * 2;
            const float b0 = bias ? bias[c0]     : 0.f;
            const float b1 = bias ? bias[c0 + 1] : 0.f;
#pragma unroll
            for (int half = 0; half < 2; half++) {
                const int r = r0 + half * 8;
                if (r < M) {
                    const float vx = acc[mi][ni][half * 2]     + b0;
                    const float vy = acc[mi][ni][half * 2 + 1] + b1;
                    const size_t idx = (size_t)r * N + c0;
                    *(float2*)(C + idx) = make_float2(vx, vy);
                    if (dH) {
                        __half2 h = __floats2half2_rn(vx, vy);
                        float2 f = __half22float2(h);
                        dH[idx >> 1] = h;
                        dL[idx >> 1] = __floats2half2_rn(vx - f.x, vy - f.y);
                    }
                }
            }
        }
    }
}

// ---------------- split: fp32 -> (hi, lo) fp16 --------------------------------
__global__ void split_f16(const float4* __restrict__ src, __half2* __restrict__ dh,
                          __half2* __restrict__ dl, int n4) {
    int i = blockIdx.x * blockDim.x + threadIdx.x;
    if (i < n4) {
        float4 v = src[i];
        __half2 h0 = __floats2half2_rn(v.x, v.y);
        __half2 h1 = __floats2half2_rn(v.z, v.w);
        float2 f0 = __half22float2(h0);
        float2 f1 = __half22float2(h1);
        dh[i * 2]     = h0;
        dh[i * 2 + 1] = h1;
        dl[i * 2]     = __floats2half2_rn(v.x - f0.x, v.y - f0.y);
        dl[i * 2 + 1] = __floats2half2_rn(v.z - f1.x, v.w - f1.y);
    }
}

// ---------------- h2 = relu(a+b), emitted directly as fp16 split --------------
__global__ void addrelu_split(const float4* __restrict__ a, const float4* __restrict__ b,
                              __half2* __restrict__ dh, __half2* __restrict__ dl, int n4) {
    int i = blockIdx.x * blockDim.x + threadIdx.x;
    if (i < n4) {
        float4 x = a[i], y = b[i];
        float4 v;
        v.x = fmaxf(x.x + y.x, 0.f); v.y = fmaxf(x.y + y.y, 0.f);
        v.z = fmaxf(x.z + y.z, 0.f); v.w = fmaxf(x.w + y.w, 0.f);
        __half2 h0 = __floats2half2_rn(v.x, v.y);
        __half2 h1 = __floats2half2_rn(v.z, v.w);
        float2 f0 = __half22float2(h0);
        float2 f1 = __half22float2(h1);
        dh[i * 2]     = h0;
        dh[i * 2 + 1] = h1;
        dl[i * 2]     = __floats2half2_rn(v.x - f0.x, v.y - f0.y);
        dl[i * 2 + 1] = __floats2half2_rn(v.z - f1.x, v.w - f1.y);
    }
}

// ---------------- final: c = relu(a+b) fp32 -----------------------------------
__global__ void add_relu4(const float4* __restrict__ a, const float4* __restrict__ b,
                          float4* __restrict__ c, int n4) {
    int i = blockIdx.x * blockDim.x + threadIdx.x;
    if (i < n4) {
        float4 x = a[i], y = b[i];
        float4 r;
        r.x = fmaxf(x.x + y.x, 0.f); r.y = fmaxf(x.y + y.y, 0.f);
        r.z = fmaxf(x.z + y.z, 0.f); r.w = fmaxf(x.w + y.w, 0.f);
        c[i] = r;
    }
}

// ---------------- bias for fused k|P GEMM: [k_b, zeros] -----------------------
__global__ void build_bias_kp(const float* __restrict__ kb, float* __restrict__ dst) {
    int i = blockIdx.x * blockDim.x + threadIdx.x;
    if (i < 2048) dst[i] = (i < 1024) ? kb[i] : 0.f;
}

// ---------------- dual pos weights v2: one block per n, weights loaded once ---
// W{1,2}[n][g][m] = max(relu(pos_emb[n,m]·pw{1,2}[g] + pb{1,2}[g]), 1e-6)
__global__ __launch_bounds__(256)
void pos_dual(const float* __restrict__ pos_emb,
              const float* __restrict__ pw1, const float* __restrict__ pb1,
              const float* __restrict__ pw2, const float* __restrict__ pb2,
              float* __restrict__ W1, float* __restrict__ W2) {
    const int n = blockIdx.x;
    __shared__ float pws[32][65];   // rows 0..15: layer1, 16..31: layer2
    __shared__ float pbs[32];
    __shared__ float pe[32][65];
    const int tid = threadIdx.x;

    if (tid < 16) pbs[tid] = pb1[tid];
    else if (tid < 32) pbs[tid] = pb2[tid - 16];
    {   // weights: 32 rows x 64, each thread 8 floats
        int row = tid >> 3;
        int c = (tid & 7) * 8;
        const float* src = (row < 16) ? pw1 + row * 64 + c : pw2 + (row - 16) * 64 + c;
        float4 v0 = *(const float4*)src;
        float4 v1 = *(const float4*)(src + 4);
        pws[row][c + 0] = v0.x; pws[row][c + 1] = v0.y;
        pws[row][c + 2] = v0.z; pws[row][c + 3] = v0.w;
        pws[row][c + 4] = v1.x; pws[row][c + 5] = v1.y;
        pws[row][c + 6] = v1.z; pws[row][c + 7] = v1.w;
    }
    __syncthreads();

    const int w = tid >> 5, lane = tid & 31;
    const int g0 = w * 2, g1 = g0 + 1;
    const float b10 = pbs[g0], b11 = pbs[g1];
    const float b20 = pbs[16 + g0], b21 = pbs[16 + g1];
    const size_t nbase = (size_t)n * GW_STRIDE;

    for (int mc = 0; mc < 10; mc++) {
        const int m0 = mc * 32;
        {   // pe chunk: 32 rows x 64, each thread 8 floats
            int r = tid >> 3;
            int c = (tid & 7) * 8;
            int m = m0 + r;
            if (m < NONGT) {
                const float* src = pos_emb + ((size_t)n * NONGT + m) * EMB + c;
                float4 v0 = *(const float4*)src;
                float4 v1 = *(const float4*)(src + 4);
                pe[r][c + 0] = v0.x; pe[r][c + 1] = v0.y;
                pe[r][c + 2] = v0.z; pe[r][c + 3] = v0.w;
                pe[r][c + 4] = v1.x; pe[r][c + 5] = v1.y;
                pe[r][c + 6] = v1.z; pe[r][c + 7] = v1.w;
            }
        }
        __syncthreads();

        float a10 = b10, a11 = b11, a20 = b20, a21 = b21;
#pragma unroll
        for (int e = 0; e < 64; e++) {
            float p = pe[lane][e];
            a10 = fmaf(p, pws[g0][e],      a10);
            a11 = fmaf(p, pws[g1][e],      a11);
            a20 = fmaf(p, pws[16 + g0][e], a20);
            a21 = fmaf(p, pws[16 + g1][e], a21);
        }
        const int m = m0 + lane;
        if (m < NONGT) {
            W1[nbase + g0 * NONGT + m] = fmaxf(a10, 1e-6f);
            W1[nbase + g1 * NONGT + m] = fmaxf(a11, 1e-6f);
            W2[nbase + g0 * NONGT + m] = fmaxf(a20, 1e-6f);
            W2[nbase + g1 * NONGT + m] = fmaxf(a21, 1e-6f);
        }
        __syncthreads();
    }
}

// ---------------- aff: Aff[n][g][m] = 0.125 * q[n,g,:]·k[m,g,:] (pure store) --
__global__ __launch_bounds__(256)
void aff_add(const float* __restrict__ Q, const float* __restrict__ Kt, int ldk,
             float* __restrict__ Aff) {
    const int g  = blockIdx.z;
    const int n0 = blockIdx.y * 64;
    const int m0 = blockIdx.x * 64;
    __shared__ float qs[64][68];
    __shared__ float ks[64][68];
    const int tid = threadIdx.x;
    const int row = tid >> 2;
    const int c0  = tid & 3;

    const float* qbase = Q + (size_t)(n0 + row) * FEAT + g * DG;
#pragma unroll
    for (int i = 0; i < 4; i++) {
        int d = (c0 + 4 * i) * 4;
        float4 v = *(const float4*)(qbase + d);
        qs[d + 0][row] = v.x; qs[d + 1][row] = v.y;
        qs[d + 2][row] = v.z; qs[d + 3][row] = v.w;
    }
    const int mrow = m0 + row;
#pragma unroll
    for (int i = 0; i < 4; i++) {
        int d = (c0 + 4 * i) * 4;
        float4 v = make_float4(0.f, 0.f, 0.f, 0.f);
        if (mrow < NONGT) v = *(const float4*)(Kt + (size_t)mrow * ldk + g * DG + d);
        ks[d + 0][row] = v.x; ks[d + 1][row] = v.y;
        ks[d + 2][row] = v.z; ks[d + 3][row] = v.w;
    }
    __syncthreads();

    const int tx = tid & 15, ty = tid >> 4;
    float acc[4][4];
#pragma unroll
    for (int i = 0; i < 4; i++)
#pragma unroll
        for (int j = 0; j < 4; j++) acc[i][j] = 0.f;
#pragma unroll
    for (int d = 0; d < 64; d++) {
        float a[4], b[4];
        *(float4*)a = *(const float4*)&qs[d][ty * 4];
        *(float4*)b = *(const float4*)&ks[d][tx * 4];
#pragma unroll
        for (int i = 0; i < 4; i++)
#pragma unroll
            for (int j = 0; j < 4; j++) acc[i][j] = fmaf(a[i], b[j], acc[i][j]);
    }

#pragma unroll
    for (int i = 0; i < 4; i++) {
        int n = n0 + ty * 4 + i;
        float* arow = Aff + (size_t)n * GW_STRIDE + g * NONGT;
#pragma unroll
        for (int j = 0; j < 4; j++) {
            int m = m0 + tx * 4 + j;
            if (m < NONGT) arow[m] = 0.125f * acc[i][j];
        }
    }
}

// ---------------- softmax(w * e^aff) over m + out = s @ P_g + out_b ----------
__global__ __launch_bounds__(256)
void softmax_pv(const float* __restrict__ Wt, const float* __restrict__ Aff,
                const float* __restrict__ P, int ldp,
                const float* __restrict__ ob, float* __restrict__ Att) {
    const int g  = blockIdx.y;
    const int n0 = blockIdx.x * 16;
    __shared__ float s[16][301];
    const int tid = threadIdx.x, w = tid >> 5, lane = tid & 31;

#pragma unroll
    for (int rr = 0; rr < 2; rr++) {
        int r = w * 2 + rr;
        const float* srcW = Wt  + (size_t)(n0 + r) * GW_STRIDE + g * NONGT;
        const float* srcA = Aff + (size_t)(n0 + r) * GW_STRIDE + g * NONGT;
        float a[10], wv[10];
        float mx = -1e30f;
#pragma unroll
        for (int i = 0; i < 10; i++) {
            int m = lane + 32 * i;
            a[i]  = (m < NONGT) ? srcA[m] : -1e30f;
            wv[i] = (m < NONGT) ? srcW[m] : 0.f;
            mx = fmaxf(mx, a[i]);
        }
#pragma unroll
        for (int off = 16; off; off >>= 1) mx = fmaxf(mx, __shfl_xor_sync(~0u, mx, off));
        float sum = 0.f;
#pragma unroll
        for (int i = 0; i < 10; i++) {
            float e = wv[i] * __expf(a[i] - mx);
            a[i] = e;
            sum += e;
        }
#pragma unroll
        for (int off = 16; off; off >>= 1) sum += __shfl_xor_sync(~0u, sum, off);
        float inv = 1.f / sum;
#pragma unroll
        for (int i = 0; i < 10; i++) {
            int m = lane + 32 * i;
            if (m < NONGT) s[r][m] = a[i] * inv;
        }
    }
    __syncthreads();

    const int o = tid & 63, grp = tid >> 6;
    float acc0 = 0.f, acc1 = 0.f, acc2 = 0.f, acc3 = 0.f;
    const float* pcol = P + g * DG + o;
#pragma unroll 4
    for (int m = 0; m < NONGT; m++) {
        float p = __ldg(pcol + (size_t)m * ldp);
        acc0 = fmaf(s[grp][m],      p, acc0);
        acc1 = fmaf(s[grp + 4][m],  p, acc1);
        acc2 = fmaf(s[grp + 8][m],  p, acc2);
        acc3 = fmaf(s[grp + 12][m], p, acc3);
    }
    float b = ob[g * DG + o];
    Att[(size_t)(n0 + grp)      * FEAT + g * DG + o] = acc0 + b;
    Att[(size_t)(n0 + grp + 4)  * FEAT + g * DG + o] = acc1 + b;
    Att[(size_t)(n0 + grp + 8)  * FEAT + g * DG + o] = acc2 + b;
    Att[(size_t)(n0 + grp + 12) * FEAT + g * DG + o] = acc3 + b;
}

// ---------------- host-side helpers -------------------------------------------
static inline void split_launch(const float* src, __half* dh, __half* dl, int n) {
    int n4 = n / 4;
    split_f16<<<(n4 + 255) / 256, 256>>>((const float4*)src, (__half2*)dh, (__half2*)dl, n4);
}
static inline void gemm_launch(const __half* ah, const __half* al,
                               const __half* wh, const __half* wl,
                               const float* bias, float* c, int M, int N, int K,
                               __half* dh = nullptr, __half* dl = nullptr) {
    dim3 grid(N / 128, (M + 127) / 128);
    gemm_lm<<<grid, 512, GSMEM>>>(ah, al, wh, wl, bias, c,
                                  (__half2*)dh, (__half2*)dl, M, N, K);
}

extern "C" void kernel_launch(void* const* d_in, const int* in_sizes, int n_in,
                              void* d_out, int out_size) {
    const float* x       = (const float*)d_in[0];
    const float* pos_emb = (const float*)d_in[1];
    const float* fc6_w   = (const float*)d_in[2];
    const float* fc6_b   = (const float*)d_in[3];
    const float* fc7_w   = (const float*)d_in[4];
    const float* fc7_b   = (const float*)d_in[5];
    const float* a1[8];
    const float* a2[8];
    for (int i = 0; i < 8; i++) a1[i] = (const float*)d_in[6 + i];
    for (int i = 0; i < 8; i++) a2[i] = (const float*)d_in[14 + i];
    // per block: pos_w, pos_b, q_w, q_b, k_w, k_b, out_w, out_b

    cudaFuncSetAttribute(gemm_lm, cudaFuncAttributeMaxDynamicSharedMemorySize, GSMEM);

    float *p_h, *p_h2, *p_q, *p_att, *p_kp, *p_w1, *p_w2, *p_aff, *p_bkp;
    cudaGetSymbolAddress((void**)&p_h,   g_h);
    cudaGetSymbolAddress((void**)&p_h2,  g_h2);
    cudaGetSymbolAddress((void**)&p_q,   g_q);
    cudaGetSymbolAddress((void**)&p_att, g_att);
    cudaGetSymbolAddress((void**)&p_kp,  g_kp);
    cudaGetSymbolAddress((void**)&p_w1,  g_w1);
    cudaGetSymbolAddress((void**)&p_w2,  g_w2);
    cudaGetSymbolAddress((void**)&p_aff, g_aff);
    cudaGetSymbolAddress((void**)&p_bkp, g_bkp);

    __half *xh, *xl, *w6h, *w6l, *w7h, *w7l, *qwh, *qwl, *kpwh, *kpwl;
    __half *ahh, *all, *bhh, *bll;
    cudaGetSymbolAddress((void**)&xh,   g_xh);
    cudaGetSymbolAddress((void**)&xl,   g_xl);
    cudaGetSymbolAddress((void**)&w6h,  g_w6h);
    cudaGetSymbolAddress((void**)&w6l,  g_w6l);
    cudaGetSymbolAddress((void**)&w7h,  g_w7h);
    cudaGetSymbolAddress((void**)&w7l,  g_w7l);
    cudaGetSymbolAddress((void**)&qwh,  g_qwh);
    cudaGetSymbolAddress((void**)&qwl,  g_qwl);
    cudaGetSymbolAddress((void**)&kpwh, g_kpwh);
    cudaGetSymbolAddress((void**)&kpwl, g_kpwl);
    cudaGetSymbolAddress((void**)&ahh,  g_ah);
    cudaGetSymbolAddress((void**)&all,  g_al);
    cudaGetSymbolAddress((void**)&bhh,  g_bh);
    cudaGetSymbolAddress((void**)&bll,  g_bl);

    const int n4 = NTOK * FEAT / 4;

    // ---- fc6 (fused split out -> ahh/all) + both pos-weight passes ----
    split_launch(x,     xh,  xl,  NTOK * IN_CH);
    split_launch(fc6_w, w6h, w6l, FEAT * IN_CH);
    split_launch(fc7_w, w7h, w7l, FEAT * FEAT);
    pos_dual<<<NTOK, 256>>>(pos_emb, a1[0], a1[1], a2[0], a2[1], p_w1, p_w2);
    gemm_launch(xh, xl, w6h, w6l, fc6_b, p_h, NTOK, FEAT, IN_CH, ahh, all);

    // ---- attention 1 (A input: ahh/all) ----
    split_launch(a1[2], qwh, qwl, FEAT * FEAT);
    split_launch(a1[4], kpwh, kpwl, FEAT * FEAT);
    split_launch(a1[6], kpwh + 1024 * FEAT, kpwl + 1024 * FEAT, FEAT * FEAT);
    build_bias_kp<<<8, 256>>>(a1[5], p_bkp);

    gemm_launch(ahh, all, qwh, qwl, a1[3], p_q, NTOK, FEAT, FEAT);
    gemm_launch(ahh, all, kpwh, kpwl, p_bkp, p_kp, NONGT, 2048, FEAT);
    aff_add<<<dim3((NONGT + 63) / 64, NTOK / 64, G), 256>>>(p_q, p_kp, 2048, p_aff);
    softmax_pv<<<dim3(NTOK / 16, G), 256>>>(p_w1, p_aff, p_kp + 1024, 2048, a1[7], p_att);

    // ---- h2 = relu(h + att1), split -> bhh/bll (fc7 input) ----
    addrelu_split<<<(n4 + 255) / 256, 256>>>((const float4*)p_h, (const float4*)p_att,
                                             (__half2*)bhh, (__half2*)bll, n4);

    // ---- fc7 (reads bhh/bll, fused split out -> ahh/all for attention 2) ----
    gemm_launch(bhh, bll, w7h, w7l, fc7_b, p_h2, NTOK, FEAT, FEAT, ahh, all);

    // ---- attention 2 (A input: ahh/all) ----
    split_launch(a2[2], qwh, qwl, FEAT * FEAT);
    split_launch(a2[4], kpwh, kpwl, FEAT * FEAT);
    split_launch(a2[6], kpwh + 1024 * FEAT, kpwl + 1024 * FEAT, FEAT * FEAT);
    build_bias_kp<<<8, 256>>>(a2[5], p_bkp);

    gemm_launch(ahh, all, qwh, qwl, a2[3], p_q, NTOK, FEAT, FEAT);
    gemm_launch(ahh, all, kpwh, kpwl, p_bkp, p_kp, NONGT, 2048, FEAT);
    aff_add<<<dim3((NONGT + 63) / 64, NTOK / 64, G), 256>>>(p_q, p_kp, 2048, p_aff);
    softmax_pv<<<dim3(NTOK / 16, G), 256>>>(p_w2, p_aff, p_kp + 1024, 2048, a2[7], p_att);

    // ---- out = relu(h2 + att2) ----
    add_relu4<<<(n4 + 255) / 256, 256>>>((const float4*)p_h2, (const float4*)p_att,
                                         (float4*)d_out, n4);
}